// round 1
// baseline (speedup 1.0000x reference)
#include <cuda_runtime.h>
#include <math.h>
#include <stdint.h>

// Problem constants (fixed by setup_inputs)
#define BB 8
#define NN 100
#define HWD 25600
#define KCLS 80
#define TT 160
#define MT 20
#define BNR (BB*NN)            // 800
#define SPLITS 4
#define KCHUNK (HWD/SPLITS)    // 6400

// Scratch (allocation-free rule: __device__ globals)
__device__ float g_part[SPLITS*BNR*TT];   // split-K partial dot products
__device__ float g_pnorm[BNR];
__device__ float g_tnorm[TT];
__device__ float g_cc[BNR*KCLS];          // focal class cost table

// ---------------------------------------------------------------------------
// Row sum-of-squares: one block per row, float4 loads, tree reduce.
// ---------------------------------------------------------------------------
__global__ void norms_kernel(const float* __restrict__ x, float* __restrict__ out)
{
    int row = blockIdx.x;
    const float4* p = (const float4*)(x + (size_t)row * HWD);
    float s = 0.f;
    for (int i = threadIdx.x; i < HWD/4; i += blockDim.x) {
        float4 v = p[i];
        s += v.x*v.x + v.y*v.y + v.z*v.z + v.w*v.w;
    }
    __shared__ float red[256];
    red[threadIdx.x] = s;
    __syncthreads();
    for (int o = 128; o; o >>= 1) {
        if (threadIdx.x < o) red[threadIdx.x] += red[threadIdx.x + o];
        __syncthreads();
    }
    if (threadIdx.x == 0) out[row] = red[0];
}

// ---------------------------------------------------------------------------
// Focal classification cost: cc[row][k] = pos - neg
// ---------------------------------------------------------------------------
__global__ void class_kernel(const float* __restrict__ logits)
{
    int idx = blockIdx.x * blockDim.x + threadIdx.x;
    if (idx >= BNR*KCLS) return;
    float x = logits[idx];
    float p = 1.f / (1.f + expf(-x));
    float neg = 0.75f * p * p * (-logf(1.f - p + 1e-8f));
    float pos = 0.25f * (1.f - p) * (1.f - p) * (-logf(p + 1e-8f));
    g_cc[idx] = pos - neg;
}

// ---------------------------------------------------------------------------
// fp32 NT GEMM: part[z][row][t] = sum_{k in chunk z} pm[row][k]*tm[t][k]
// 32x32 tile, 256 threads, 2x2 micro-tile via float2 LDS, split-K over z.
// Exact tiling: 800%32==0, 160%32==0, 6400%32==0.
// ---------------------------------------------------------------------------
__global__ void gemm_kernel(const float* __restrict__ A, const float* __restrict__ Bm)
{
    __shared__ __align__(16) float As[32][34];   // [k][m], stride 34 keeps float2 aligned
    __shared__ __align__(16) float Bs[32][34];   // [k][n]

    int row0 = blockIdx.x * 32;
    int col0 = blockIdx.y * 32;
    int kbase = blockIdx.z * KCHUNK;

    int tid = threadIdx.x;
    int tx = tid & 15, ty = tid >> 4;
    int lr = tid >> 3;           // 0..31 local row
    int lk = (tid & 7) * 4;      // 0,4,...,28

    const float* Arow = A  + (size_t)(row0 + lr) * HWD + lk;
    const float* Brow = Bm + (size_t)(col0 + lr) * HWD + lk;

    float acc00 = 0.f, acc01 = 0.f, acc10 = 0.f, acc11 = 0.f;

    for (int kb = kbase; kb < kbase + KCHUNK; kb += 32) {
        float4 av = *(const float4*)(Arow + kb);
        float4 bv = *(const float4*)(Brow + kb);
        __syncthreads();
        As[lk+0][lr] = av.x; As[lk+1][lr] = av.y; As[lk+2][lr] = av.z; As[lk+3][lr] = av.w;
        Bs[lk+0][lr] = bv.x; Bs[lk+1][lr] = bv.y; Bs[lk+2][lr] = bv.z; Bs[lk+3][lr] = bv.w;
        __syncthreads();
        #pragma unroll
        for (int kk = 0; kk < 32; kk++) {
            float2 a = *(const float2*)&As[kk][ty*2];
            float2 b = *(const float2*)&Bs[kk][tx*2];
            acc00 += a.x*b.x; acc01 += a.x*b.y;
            acc10 += a.y*b.x; acc11 += a.y*b.y;
        }
    }

    float* o = g_part + ((size_t)blockIdx.z * BNR + row0 + ty*2) * TT + col0 + tx*2;
    o[0] = acc00; o[1] = acc01;
    o[TT] = acc10; o[TT+1] = acc11;
}

// ---------------------------------------------------------------------------
// Assemble C = 2 * dice_score + class_cost, with nan_to_num.
// Deterministic fixed-order split-K reduction.
// ---------------------------------------------------------------------------
__global__ void assemble_kernel(const int* __restrict__ tgt_ids, float* __restrict__ out)
{
    int idx = blockIdx.x * blockDim.x + threadIdx.x;
    if (idx >= BNR*TT) return;
    int row = idx / TT, t = idx % TT;
    float dot = 0.f;
    #pragma unroll
    for (int s = 0; s < SPLITS; s++)
        dot += g_part[((size_t)s * BNR + row) * TT + t];
    float num = 2.f * dot;
    float den = g_pnorm[row] + g_tnorm[t];
    float score = -((num + 1e-4f) / (den + 1e-4f));
    float c = 2.f * score + g_cc[row * KCLS + tgt_ids[t]];
    if (!isfinite(c)) c = 0.f;
    out[idx] = c;
}

// ---------------------------------------------------------------------------
// Hungarian (Jonker-Volgenant with potentials), exact replica of reference
// _lsa on the transposed 20x100 block-diagonal slice. One warp per image.
// float64 internally, lexicographic (value, index) argmin to match np.argmin
// first-index tie-breaking.
// ---------------------------------------------------------------------------
__global__ void hungarian_kernel(const float* __restrict__ C, float* __restrict__ out)
{
    int b = blockIdx.x;
    int lane = threadIdx.x;

    __shared__ double cost[MT][NN];      // [target][pred]  (transposed slice)
    __shared__ double u[MT+1], v[NN+1], minv[NN+1];
    __shared__ int p[NN+1], way[NN+1], used[NN+1];

    // cost[r][c] = C[b, c, b*MT + r]
    for (int idx = lane; idx < MT*NN; idx += 32) {
        int r = idx / NN, c = idx % NN;
        cost[r][c] = (double)C[(size_t)(b*NN + c) * TT + b*MT + r];
    }
    for (int j = lane; j <= NN; j += 32) { v[j] = 0.0; p[j] = 0; way[j] = 0; }
    for (int j = lane; j <= MT; j += 32) u[j] = 0.0;
    __syncwarp();

    for (int i = 1; i <= MT; i++) {
        if (lane == 0) p[0] = i;
        for (int j = lane; j <= NN; j += 32) { minv[j] = 1e18; used[j] = 0; }
        __syncwarp();

        int j0 = 0;
        while (true) {
            if (lane == 0) used[j0] = 1;
            __syncwarp();
            int i0 = p[j0];
            double uu = u[i0];

            double bestv = 1e18;
            int bestj = NN + 1;
            for (int j = lane + 1; j <= NN; j += 32) {
                if (!used[j]) {
                    double cur = cost[i0-1][j-1] - uu - v[j];
                    if (cur < minv[j]) { minv[j] = cur; way[j] = j0; }
                    double mv = minv[j];
                    if (mv < bestv || (mv == bestv && j < bestj)) { bestv = mv; bestj = j; }
                }
            }
            // warp argmin with first-index tie-break
            for (int off = 16; off; off >>= 1) {
                double ov = __shfl_down_sync(0xffffffffu, bestv, off);
                int    oj = __shfl_down_sync(0xffffffffu, bestj, off);
                if (ov < bestv || (ov == bestv && oj < bestj)) { bestv = ov; bestj = oj; }
            }
            double delta = __shfl_sync(0xffffffffu, bestv, 0);
            int j1 = __shfl_sync(0xffffffffu, bestj, 0);
            __syncwarp();

            // potentials update (rows of used columns are distinct -> race-free)
            for (int j = lane; j <= NN; j += 32) {
                if (used[j]) { u[p[j]] += delta; v[j] -= delta; }
                else minv[j] -= delta;
            }
            __syncwarp();

            j0 = j1;
            if (p[j0] == 0) break;
            __syncwarp();
        }

        if (lane == 0) {   // augment along way[] chain
            int jj = j0;
            while (jj) { int jp = way[jj]; p[jj] = p[jp]; jj = jp; }
        }
        __syncwarp();
    }

    if (lane == 0) {
        int k = 0;
        for (int j = 1; j <= NN; j++) {
            if (p[j] != 0) {
                // transposed back: rows = pred index (ascending), cols = target index
                out[(size_t)BNR*TT + b*MT + k]            = (float)(j - 1);
                out[(size_t)BNR*TT + BB*MT + b*MT + k]    = (float)(p[j] - 1);
                k++;
            }
        }
    }
}

// ---------------------------------------------------------------------------
extern "C" void kernel_launch(void* const* d_in, const int* in_sizes, int n_in,
                              void* d_out, int out_size)
{
    const float* pred_masks   = (const float*)d_in[0];   // (8,100,160,160)
    const float* pred_logits  = (const float*)d_in[1];   // (8,100,80)
    const float* target_masks = (const float*)d_in[2];   // (160,160,160)
    const int*   tgt_ids      = (const int*)d_in[3];     // (160,)
    float* out = (float*)d_out;                           // C(128000) | rows(160) | cols(160)

    float* pnorm; cudaGetSymbolAddress((void**)&pnorm, g_pnorm);
    float* tnorm; cudaGetSymbolAddress((void**)&tnorm, g_tnorm);

    norms_kernel<<<BNR, 256>>>(pred_masks, pnorm);
    norms_kernel<<<TT, 256>>>(target_masks, tnorm);
    class_kernel<<<(BNR*KCLS + 255)/256, 256>>>(pred_logits);

    dim3 ggrid(BNR/32, TT/32, SPLITS);   // 25 x 5 x 4
    gemm_kernel<<<ggrid, 256>>>(pred_masks, target_masks);

    assemble_kernel<<<(BNR*TT + 255)/256, 256>>>(tgt_ids, out);

    hungarian_kernel<<<BB, 32>>>(out, out);
}

// round 2
// speedup vs baseline: 1.7438x; 1.7438x over previous
#include <cuda_runtime.h>
#include <math.h>
#include <stdint.h>

// Problem constants (fixed by setup_inputs)
#define BB 8
#define NN 100
#define HWD 25600
#define KCLS 80
#define TT 160
#define MT 20
#define BNR (BB*NN)            // 800

// GEMM tiling
#define BM 80
#define BN 32
#define BKK 16
#define SPLITS 8
#define KSPL (HWD/SPLITS)      // 3200
#define NITER (KSPL/BKK)       // 200

// Scratch (allocation-free rule: __device__ globals)
__device__ float g_part[SPLITS*BNR*TT];   // split-K partial dot products
__device__ float g_pnorm[BNR];
__device__ float g_tnorm[TT];
__device__ float g_cc[BNR*KCLS];          // focal class cost table

// ---------------------------------------------------------------------------
// Row sum-of-squares: one block per row, float4 loads, tree reduce.
// ---------------------------------------------------------------------------
__global__ void norms_kernel(const float* __restrict__ x, float* __restrict__ out)
{
    int row = blockIdx.x;
    const float4* p = (const float4*)(x + (size_t)row * HWD);
    float s = 0.f;
    for (int i = threadIdx.x; i < HWD/4; i += blockDim.x) {
        float4 v = p[i];
        s += v.x*v.x + v.y*v.y + v.z*v.z + v.w*v.w;
    }
    __shared__ float red[256];
    red[threadIdx.x] = s;
    __syncthreads();
    for (int o = 128; o; o >>= 1) {
        if (threadIdx.x < o) red[threadIdx.x] += red[threadIdx.x + o];
        __syncthreads();
    }
    if (threadIdx.x == 0) out[row] = red[0];
}

// ---------------------------------------------------------------------------
// Focal classification cost: cc[row][k] = pos - neg
// ---------------------------------------------------------------------------
__global__ void class_kernel(const float* __restrict__ logits)
{
    int idx = blockIdx.x * blockDim.x + threadIdx.x;
    if (idx >= BNR*KCLS) return;
    float x = logits[idx];
    float p = 1.f / (1.f + expf(-x));
    float neg = 0.75f * p * p * (-logf(1.f - p + 1e-8f));
    float pos = 0.25f * (1.f - p) * (1.f - p) * (-logf(p + 1e-8f));
    g_cc[idx] = pos - neg;
}

// ---------------------------------------------------------------------------
// fp32 NT GEMM: part[z][row][t] = sum_{k in chunk z} pm[row][k]*tm[t][k]
// BM=80 x BN=32 tile, 160 threads, 4x4 micro-tile, float4 fragments,
// register-prefetch pipeline, split-K over blockIdx.z.
// All dims divide exactly: 800/80, 160/32, 3200/16 -> no bounds checks.
// ---------------------------------------------------------------------------
__global__ void __launch_bounds__(160) gemm_kernel(const float* __restrict__ A,
                                                   const float* __restrict__ Bm)
{
    __shared__ __align__(16) float As[BKK][84];   // [k][m], stride mult-of-4 floats
    __shared__ __align__(16) float Bs[BKK][36];   // [k][n]

    int row0 = blockIdx.x * BM;
    int col0 = blockIdx.y * BN;
    size_t kbase = (size_t)blockIdx.z * KSPL;

    int tid = threadIdx.x;
    int tx = tid & 7;            // 0..7  -> 32 cols / 4
    int ty = tid >> 3;           // 0..19 -> 80 rows / 4

    // A tile: 80 rows x 16 k = 320 float4 (r = idx/4, k-quad = idx%4)
    int ra0 = tid >> 2,        ka0 = (tid & 3) * 4;          // idx0 = tid
    int idx1 = tid + 160;
    int ra1 = idx1 >> 2,       ka1 = (idx1 & 3) * 4;         // idx1
    const float* Aptr0 = A + (size_t)(row0 + ra0) * HWD + kbase + ka0;
    const float* Aptr1 = A + (size_t)(row0 + ra1) * HWD + kbase + ka1;

    // B tile: 32 rows x 16 k = 128 float4 (threads < 128)
    int rb = tid >> 2,         kb = (tid & 3) * 4;
    const float* Bptr = Bm + (size_t)(col0 + rb) * HWD + kbase + kb;
    bool bact = (tid < 128);

    float4 a0 = *(const float4*)Aptr0;
    float4 a1 = *(const float4*)Aptr1;
    float4 b0 = bact ? *(const float4*)Bptr : make_float4(0,0,0,0);

    float acc[4][4] = {};

    for (int it = 0; it < NITER; it++) {
        As[ka0+0][ra0] = a0.x; As[ka0+1][ra0] = a0.y; As[ka0+2][ra0] = a0.z; As[ka0+3][ra0] = a0.w;
        As[ka1+0][ra1] = a1.x; As[ka1+1][ra1] = a1.y; As[ka1+2][ra1] = a1.z; As[ka1+3][ra1] = a1.w;
        if (bact) {
            Bs[kb+0][rb] = b0.x; Bs[kb+1][rb] = b0.y; Bs[kb+2][rb] = b0.z; Bs[kb+3][rb] = b0.w;
        }
        __syncthreads();

        if (it + 1 < NITER) {            // prefetch next tile while computing
            int off = (it + 1) * BKK;
            a0 = *(const float4*)(Aptr0 + off);
            a1 = *(const float4*)(Aptr1 + off);
            if (bact) b0 = *(const float4*)(Bptr + off);
        }

        #pragma unroll
        for (int k = 0; k < BKK; k++) {
            float4 av = *(const float4*)&As[k][ty*4];
            float4 bv = *(const float4*)&Bs[k][tx*4];
            acc[0][0] += av.x*bv.x; acc[0][1] += av.x*bv.y; acc[0][2] += av.x*bv.z; acc[0][3] += av.x*bv.w;
            acc[1][0] += av.y*bv.x; acc[1][1] += av.y*bv.y; acc[1][2] += av.y*bv.z; acc[1][3] += av.y*bv.w;
            acc[2][0] += av.z*bv.x; acc[2][1] += av.z*bv.y; acc[2][2] += av.z*bv.z; acc[2][3] += av.z*bv.w;
            acc[3][0] += av.w*bv.x; acc[3][1] += av.w*bv.y; acc[3][2] += av.w*bv.z; acc[3][3] += av.w*bv.w;
        }
        __syncthreads();
    }

    float* o = g_part + ((size_t)blockIdx.z * BNR + row0 + ty*4) * TT + col0 + tx*4;
    #pragma unroll
    for (int i = 0; i < 4; i++) {
        float4 v = make_float4(acc[i][0], acc[i][1], acc[i][2], acc[i][3]);
        *(float4*)(o + (size_t)i * TT) = v;
    }
}

// ---------------------------------------------------------------------------
// Assemble C = 2 * dice_score + class_cost, with nan_to_num.
// Deterministic fixed-order split-K reduction.
// ---------------------------------------------------------------------------
__global__ void assemble_kernel(const int* __restrict__ tgt_ids, float* __restrict__ out)
{
    int idx = blockIdx.x * blockDim.x + threadIdx.x;
    if (idx >= BNR*TT) return;
    int row = idx / TT, t = idx % TT;
    float dot = 0.f;
    #pragma unroll
    for (int s = 0; s < SPLITS; s++)
        dot += g_part[((size_t)s * BNR + row) * TT + t];
    float num = 2.f * dot;
    float den = g_pnorm[row] + g_tnorm[t];
    float score = -((num + 1e-4f) / (den + 1e-4f));
    float c = 2.f * score + g_cc[row * KCLS + tgt_ids[t]];
    if (!isfinite(c)) c = 0.f;
    out[idx] = c;
}

// ---------------------------------------------------------------------------
// Hungarian (Jonker-Volgenant with potentials), exact replica of reference
// _lsa on the transposed 20x100 block-diagonal slice. One warp per image.
// ---------------------------------------------------------------------------
__global__ void hungarian_kernel(const float* __restrict__ C, float* __restrict__ out)
{
    int b = blockIdx.x;
    int lane = threadIdx.x;

    __shared__ double cost[MT][NN];      // [target][pred]  (transposed slice)
    __shared__ double u[MT+1], v[NN+1], minv[NN+1];
    __shared__ int p[NN+1], way[NN+1], used[NN+1];

    for (int idx = lane; idx < MT*NN; idx += 32) {
        int r = idx / NN, c = idx % NN;
        cost[r][c] = (double)C[(size_t)(b*NN + c) * TT + b*MT + r];
    }
    for (int j = lane; j <= NN; j += 32) { v[j] = 0.0; p[j] = 0; way[j] = 0; }
    for (int j = lane; j <= MT; j += 32) u[j] = 0.0;
    __syncwarp();

    for (int i = 1; i <= MT; i++) {
        if (lane == 0) p[0] = i;
        for (int j = lane; j <= NN; j += 32) { minv[j] = 1e18; used[j] = 0; }
        __syncwarp();

        int j0 = 0;
        while (true) {
            if (lane == 0) used[j0] = 1;
            __syncwarp();
            int i0 = p[j0];
            double uu = u[i0];

            double bestv = 1e18;
            int bestj = NN + 1;
            for (int j = lane + 1; j <= NN; j += 32) {
                if (!used[j]) {
                    double cur = cost[i0-1][j-1] - uu - v[j];
                    if (cur < minv[j]) { minv[j] = cur; way[j] = j0; }
                    double mv = minv[j];
                    if (mv < bestv || (mv == bestv && j < bestj)) { bestv = mv; bestj = j; }
                }
            }
            for (int off = 16; off; off >>= 1) {
                double ov = __shfl_down_sync(0xffffffffu, bestv, off);
                int    oj = __shfl_down_sync(0xffffffffu, bestj, off);
                if (ov < bestv || (ov == bestv && oj < bestj)) { bestv = ov; bestj = oj; }
            }
            double delta = __shfl_sync(0xffffffffu, bestv, 0);
            int j1 = __shfl_sync(0xffffffffu, bestj, 0);
            __syncwarp();

            for (int j = lane; j <= NN; j += 32) {
                if (used[j]) { u[p[j]] += delta; v[j] -= delta; }
                else minv[j] -= delta;
            }
            __syncwarp();

            j0 = j1;
            if (p[j0] == 0) break;
            __syncwarp();
        }

        if (lane == 0) {
            int jj = j0;
            while (jj) { int jp = way[jj]; p[jj] = p[jp]; jj = jp; }
        }
        __syncwarp();
    }

    if (lane == 0) {
        int k = 0;
        for (int j = 1; j <= NN; j++) {
            if (p[j] != 0) {
                out[(size_t)BNR*TT + b*MT + k]            = (float)(j - 1);
                out[(size_t)BNR*TT + BB*MT + b*MT + k]    = (float)(p[j] - 1);
                k++;
            }
        }
    }
}

// ---------------------------------------------------------------------------
extern "C" void kernel_launch(void* const* d_in, const int* in_sizes, int n_in,
                              void* d_out, int out_size)
{
    const float* pred_masks   = (const float*)d_in[0];   // (8,100,160,160)
    const float* pred_logits  = (const float*)d_in[1];   // (8,100,80)
    const float* target_masks = (const float*)d_in[2];   // (160,160,160)
    const int*   tgt_ids      = (const int*)d_in[3];     // (160,)
    float* out = (float*)d_out;                           // C(128000) | rows(160) | cols(160)

    float* pnorm; cudaGetSymbolAddress((void**)&pnorm, g_pnorm);
    float* tnorm; cudaGetSymbolAddress((void**)&tnorm, g_tnorm);

    norms_kernel<<<BNR, 256>>>(pred_masks, pnorm);
    norms_kernel<<<TT, 256>>>(target_masks, tnorm);
    class_kernel<<<(BNR*KCLS + 255)/256, 256>>>(pred_logits);

    dim3 ggrid(BNR/BM, TT/BN, SPLITS);   // 10 x 5 x 8 = 400
    gemm_kernel<<<ggrid, 160>>>(pred_masks, target_masks);

    assemble_kernel<<<(BNR*TT + 255)/256, 256>>>(tgt_ids, out);

    hungarian_kernel<<<BB, 32>>>(out, out);
}

// round 4
// speedup vs baseline: 2.7162x; 1.5576x over previous
#include <cuda_runtime.h>
#include <math.h>
#include <stdint.h>

// Problem constants (fixed by setup_inputs)
#define BB 8
#define NN 100
#define HWD 25600
#define KCLS 80
#define TT 160
#define MT 20
#define BNR (BB*NN)            // 800

// GEMM config
#define SPLITS 21
#define BKF 32                 // fp32 K per chunk
#define NCH (HWD/BKF)          // 800 chunks total

// Scratch (allocation-free rule: __device__ globals)
__device__ float g_part[SPLITS*BNR*TT];   // split-K partial dot products
__device__ float g_pnorm[BNR];
__device__ float g_tnorm[TT];
__device__ float g_cc[BNR*KCLS];          // focal class cost table

// ---------------------------------------------------------------------------
// Row sum-of-squares
// ---------------------------------------------------------------------------
__global__ void norms_kernel(const float* __restrict__ x, float* __restrict__ out)
{
    int row = blockIdx.x;
    const float4* p = (const float4*)(x + (size_t)row * HWD);
    float s = 0.f;
    for (int i = threadIdx.x; i < HWD/4; i += blockDim.x) {
        float4 v = p[i];
        s += v.x*v.x + v.y*v.y + v.z*v.z + v.w*v.w;
    }
    __shared__ float red[256];
    red[threadIdx.x] = s;
    __syncthreads();
    for (int o = 128; o; o >>= 1) {
        if (threadIdx.x < o) red[threadIdx.x] += red[threadIdx.x + o];
        __syncthreads();
    }
    if (threadIdx.x == 0) out[row] = red[0];
}

// ---------------------------------------------------------------------------
// Focal classification cost
// ---------------------------------------------------------------------------
__global__ void class_kernel(const float* __restrict__ logits)
{
    int idx = blockIdx.x * blockDim.x + threadIdx.x;
    if (idx >= BNR*KCLS) return;
    float x = logits[idx];
    float p = 1.f / (1.f + expf(-x));
    float neg = 0.75f * p * p * (-logf(1.f - p + 1e-8f));
    float pos = 0.25f * (1.f - p) * (1.f - p) * (-logf(p + 1e-8f));
    g_cc[idx] = pos - neg;
}

// ---------------------------------------------------------------------------
// 3xTF32 mma.sync GEMM: part[z][row][t] = sum_{k in split z} pm[row][k]*tm[t][k]
// CTA tile 128(M) x 160(N, full) x 32(K). 8 warps = 4m x 2n.
// Warp tile 32x80: 2 m-frags (m16) x 10 n-frags (n8), mma.m16n8k8.tf32.
// Each fp32 split into tf32 hi+lo; products hi*hi + hi*lo + lo*hi.
// ---------------------------------------------------------------------------
#define SM_AH 0
#define SM_AL 4608              // 128*36
#define SM_BH 9216
#define SM_BL 14976             // + 160*36
#define SM_WORDS 20736          // 82944 bytes

__device__ __forceinline__ void tf32_split(float f, uint32_t& h, uint32_t& l)
{
    asm("cvt.rna.tf32.f32 %0, %1;" : "=r"(h) : "f"(f));
    float r = f - __uint_as_float(h);
    asm("cvt.rna.tf32.f32 %0, %1;" : "=r"(l) : "f"(r));
}

#define MMA1688(d, a, b0, b1) \
    asm volatile("mma.sync.aligned.m16n8k8.row.col.f32.tf32.tf32.f32 " \
        "{%0,%1,%2,%3}, {%4,%5,%6,%7}, {%8,%9}, {%0,%1,%2,%3};" \
        : "+f"((d)[0]), "+f"((d)[1]), "+f"((d)[2]), "+f"((d)[3]) \
        : "r"((a)[0]), "r"((a)[1]), "r"((a)[2]), "r"((a)[3]), "r"(b0), "r"(b1))

__global__ void __launch_bounds__(256, 1) gemm_tf32(const float* __restrict__ A,
                                                     const float* __restrict__ Bm)
{
    extern __shared__ __align__(16) uint32_t sm[];

    const int tid = threadIdx.x;
    const int wid = tid >> 5, lane = tid & 31;
    const int wm = wid >> 1, wn = wid & 1;
    const int lr = lane >> 2, lc = lane & 3;

    const int row0 = blockIdx.x * 128;
    const int z = blockIdx.y;
    const int cbeg = (z * NCH) / SPLITS;
    const int cend = ((z + 1) * NCH) / SPLITS;

    // producer indexing (float4 granularity): row = idx>>3, quad = idx&7
    float4 pa[4], pb[5];
    {
        size_t kb = (size_t)cbeg * BKF;
        #pragma unroll
        for (int i = 0; i < 4; i++) {
            int idx = tid + i * 256, ar = idx >> 3, q = idx & 7;
            int garow = row0 + ar;
            pa[i] = (garow < BNR) ? *(const float4*)(A + (size_t)garow * HWD + kb + q * 4)
                                  : make_float4(0,0,0,0);
        }
        #pragma unroll
        for (int i = 0; i < 5; i++) {
            int idx = tid + i * 256, br = idx >> 3, q = idx & 7;
            pb[i] = *(const float4*)(Bm + (size_t)br * HWD + kb + q * 4);
        }
    }

    float acc[2][10][4];
    #pragma unroll
    for (int f = 0; f < 2; f++)
        #pragma unroll
        for (int nf = 0; nf < 10; nf++)
            #pragma unroll
            for (int e = 0; e < 4; e++) acc[f][nf][e] = 0.f;

    for (int c = cbeg; c < cend; c++) {
        __syncthreads();
        // ---- store hi/lo tf32 tiles (stride 36 words, 16B-aligned vectors)
        #pragma unroll
        for (int i = 0; i < 4; i++) {
            int idx = tid + i * 256, ar = idx >> 3, q = idx & 7;
            uint4 hv, lv;
            tf32_split(pa[i].x, hv.x, lv.x); tf32_split(pa[i].y, hv.y, lv.y);
            tf32_split(pa[i].z, hv.z, lv.z); tf32_split(pa[i].w, hv.w, lv.w);
            *(uint4*)(sm + SM_AH + ar * 36 + q * 4) = hv;
            *(uint4*)(sm + SM_AL + ar * 36 + q * 4) = lv;
        }
        #pragma unroll
        for (int i = 0; i < 5; i++) {
            int idx = tid + i * 256, br = idx >> 3, q = idx & 7;
            uint4 hv, lv;
            tf32_split(pb[i].x, hv.x, lv.x); tf32_split(pb[i].y, hv.y, lv.y);
            tf32_split(pb[i].z, hv.z, lv.z); tf32_split(pb[i].w, hv.w, lv.w);
            *(uint4*)(sm + SM_BH + br * 36 + q * 4) = hv;
            *(uint4*)(sm + SM_BL + br * 36 + q * 4) = lv;
        }
        __syncthreads();

        // ---- prefetch next chunk while computing this one
        if (c + 1 < cend) {
            size_t kb = (size_t)(c + 1) * BKF;
            #pragma unroll
            for (int i = 0; i < 4; i++) {
                int idx = tid + i * 256, ar = idx >> 3, q = idx & 7;
                int garow = row0 + ar;
                pa[i] = (garow < BNR) ? *(const float4*)(A + (size_t)garow * HWD + kb + q * 4)
                                      : make_float4(0,0,0,0);
            }
            #pragma unroll
            for (int i = 0; i < 5; i++) {
                int idx = tid + i * 256, br = idx >> 3, q = idx & 7;
                pb[i] = *(const float4*)(Bm + (size_t)br * HWD + kb + q * 4);
            }
        }

        // ---- compute: 4 k-steps of 8
        #pragma unroll
        for (int ks = 0; ks < 4; ks++) {
            int k0 = ks * 8;
            uint32_t ah[2][4], al[2][4];
            #pragma unroll
            for (int f = 0; f < 2; f++) {
                int m0 = wm * 32 + f * 16 + lr;
                ah[f][0] = sm[SM_AH + (m0    ) * 36 + k0 + lc];
                ah[f][1] = sm[SM_AH + (m0 + 8) * 36 + k0 + lc];
                ah[f][2] = sm[SM_AH + (m0    ) * 36 + k0 + lc + 4];
                ah[f][3] = sm[SM_AH + (m0 + 8) * 36 + k0 + lc + 4];
                al[f][0] = sm[SM_AL + (m0    ) * 36 + k0 + lc];
                al[f][1] = sm[SM_AL + (m0 + 8) * 36 + k0 + lc];
                al[f][2] = sm[SM_AL + (m0    ) * 36 + k0 + lc + 4];
                al[f][3] = sm[SM_AL + (m0 + 8) * 36 + k0 + lc + 4];
            }
            #pragma unroll
            for (int nf = 0; nf < 10; nf++) {
                int n0 = wn * 80 + nf * 8 + lr;
                uint32_t bh0 = sm[SM_BH + n0 * 36 + k0 + lc];
                uint32_t bh1 = sm[SM_BH + n0 * 36 + k0 + lc + 4];
                uint32_t bl0 = sm[SM_BL + n0 * 36 + k0 + lc];
                uint32_t bl1 = sm[SM_BL + n0 * 36 + k0 + lc + 4];
                #pragma unroll
                for (int f = 0; f < 2; f++) {
                    MMA1688(acc[f][nf], ah[f], bh0, bh1);
                    MMA1688(acc[f][nf], ah[f], bl0, bl1);
                    MMA1688(acc[f][nf], al[f], bh0, bh1);
                }
            }
        }
    }

    // ---- epilogue: write partials
    #pragma unroll
    for (int f = 0; f < 2; f++) {
        int grow0 = row0 + wm * 32 + f * 16 + lr;
        #pragma unroll
        for (int nf = 0; nf < 10; nf++) {
            int col = wn * 80 + nf * 8 + lc * 2;
            if (grow0 < BNR) {
                float* o = g_part + ((size_t)z * BNR + grow0) * TT + col;
                o[0] = acc[f][nf][0]; o[1] = acc[f][nf][1];
            }
            if (grow0 + 8 < BNR) {
                float* o = g_part + ((size_t)z * BNR + grow0 + 8) * TT + col;
                o[0] = acc[f][nf][2]; o[1] = acc[f][nf][3];
            }
        }
    }
}

// ---------------------------------------------------------------------------
// Assemble C = 2 * dice_score + class_cost (fixed-order split-K reduce)
// ---------------------------------------------------------------------------
__global__ void assemble_kernel(const int* __restrict__ tgt_ids, float* __restrict__ out)
{
    int idx = blockIdx.x * blockDim.x + threadIdx.x;
    if (idx >= BNR*TT) return;
    int row = idx / TT, t = idx % TT;
    float dot = 0.f;
    #pragma unroll
    for (int s = 0; s < SPLITS; s++)
        dot += g_part[((size_t)s * BNR + row) * TT + t];
    float num = 2.f * dot;
    float den = g_pnorm[row] + g_tnorm[t];
    float score = -((num + 1e-4f) / (den + 1e-4f));
    float c = 2.f * score + g_cc[row * KCLS + tgt_ids[t]];
    if (!isfinite(c)) c = 0.f;
    out[idx] = c;
}

// ---------------------------------------------------------------------------
// Hungarian (Jonker-Volgenant), exact replica of reference _lsa.
// ---------------------------------------------------------------------------
__global__ void hungarian_kernel(const float* __restrict__ C, float* __restrict__ out)
{
    int b = blockIdx.x;
    int lane = threadIdx.x;

    __shared__ double cost[MT][NN];
    __shared__ double u[MT+1], v[NN+1], minv[NN+1];
    __shared__ int p[NN+1], way[NN+1], used[NN+1];

    for (int idx = lane; idx < MT*NN; idx += 32) {
        int r = idx / NN, c = idx % NN;
        cost[r][c] = (double)C[(size_t)(b*NN + c) * TT + b*MT + r];
    }
    for (int j = lane; j <= NN; j += 32) { v[j] = 0.0; p[j] = 0; way[j] = 0; }
    for (int j = lane; j <= MT; j += 32) u[j] = 0.0;
    __syncwarp();

    for (int i = 1; i <= MT; i++) {
        if (lane == 0) p[0] = i;
        for (int j = lane; j <= NN; j += 32) { minv[j] = 1e18; used[j] = 0; }
        __syncwarp();

        int j0 = 0;
        while (true) {
            if (lane == 0) used[j0] = 1;
            __syncwarp();
            int i0 = p[j0];
            double uu = u[i0];

            double bestv = 1e18;
            int bestj = NN + 1;
            for (int j = lane + 1; j <= NN; j += 32) {
                if (!used[j]) {
                    double cur = cost[i0-1][j-1] - uu - v[j];
                    if (cur < minv[j]) { minv[j] = cur; way[j] = j0; }
                    double mv = minv[j];
                    if (mv < bestv || (mv == bestv && j < bestj)) { bestv = mv; bestj = j; }
                }
            }
            for (int off = 16; off; off >>= 1) {
                double ov = __shfl_down_sync(0xffffffffu, bestv, off);
                int    oj = __shfl_down_sync(0xffffffffu, bestj, off);
                if (ov < bestv || (ov == bestv && oj < bestj)) { bestv = ov; bestj = oj; }
            }
            double delta = __shfl_sync(0xffffffffu, bestv, 0);
            int j1 = __shfl_sync(0xffffffffu, bestj, 0);
            __syncwarp();

            for (int j = lane; j <= NN; j += 32) {
                if (used[j]) { u[p[j]] += delta; v[j] -= delta; }
                else minv[j] -= delta;
            }
            __syncwarp();

            j0 = j1;
            if (p[j0] == 0) break;
            __syncwarp();
        }

        if (lane == 0) {
            int jj = j0;
            while (jj) { int jp = way[jj]; p[jj] = p[jp]; jj = jp; }
        }
        __syncwarp();
    }

    if (lane == 0) {
        int k = 0;
        for (int j = 1; j <= NN; j++) {
            if (p[j] != 0) {
                out[(size_t)BNR*TT + b*MT + k]            = (float)(j - 1);
                out[(size_t)BNR*TT + BB*MT + b*MT + k]    = (float)(p[j] - 1);
                k++;
            }
        }
    }
}

// ---------------------------------------------------------------------------
extern "C" void kernel_launch(void* const* d_in, const int* in_sizes, int n_in,
                              void* d_out, int out_size)
{
    const float* pred_masks   = (const float*)d_in[0];   // (8,100,160,160)
    const float* pred_logits  = (const float*)d_in[1];   // (8,100,80)
    const float* target_masks = (const float*)d_in[2];   // (160,160,160)
    const int*   tgt_ids      = (const int*)d_in[3];     // (160,)
    float* out = (float*)d_out;                           // C(128000) | rows(160) | cols(160)

    float* pnorm; cudaGetSymbolAddress((void**)&pnorm, g_pnorm);
    float* tnorm; cudaGetSymbolAddress((void**)&tnorm, g_tnorm);

    cudaFuncSetAttribute(gemm_tf32, cudaFuncAttributeMaxDynamicSharedMemorySize,
                         SM_WORDS * 4);

    norms_kernel<<<BNR, 256>>>(pred_masks, pnorm);
    norms_kernel<<<TT, 256>>>(target_masks, tnorm);
    class_kernel<<<(BNR*KCLS + 255)/256, 256>>>(pred_logits);

    gemm_tf32<<<dim3(7, SPLITS), 256, SM_WORDS * 4>>>(pred_masks, target_masks);

    assemble_kernel<<<(BNR*TT + 255)/256, 256>>>(tgt_ids, out);

    hungarian_kernel<<<BB, 32>>>(out, out);
}

// round 5
// speedup vs baseline: 2.8675x; 1.0557x over previous
#include <cuda_runtime.h>
#include <math.h>
#include <stdint.h>

// Problem constants (fixed by setup_inputs)
#define BB 8
#define NN 100
#define HWD 25600
#define KCLS 80
#define TT 160
#define MT 20
#define BNR (BB*NN)            // 800

// GEMM config
#define SPLITS 21
#define BKF 64                 // fp32 K per chunk
#define NCH (HWD/BKF)          // 400 chunks total

// Scratch (allocation-free rule: __device__ globals)
__device__ float g_part[SPLITS*BNR*TT];   // split-K partial dot products
__device__ float g_pnp[SPLITS*BNR];       // per-split pred-norm partials
__device__ float g_tnp[SPLITS*TT];        // per-split target-norm partials
__device__ float g_pnorm[BNR];
__device__ float g_tnorm[TT];
__device__ float g_cc[BNR*KCLS];          // focal class cost table

// ---------------------------------------------------------------------------
// Focal classification cost
// ---------------------------------------------------------------------------
__global__ void class_kernel(const float* __restrict__ logits)
{
    int idx = blockIdx.x * blockDim.x + threadIdx.x;
    if (idx >= BNR*KCLS) return;
    float x = logits[idx];
    float p = 1.f / (1.f + expf(-x));
    float neg = 0.75f * p * p * (-logf(1.f - p + 1e-8f));
    float pos = 0.25f * (1.f - p) * (1.f - p) * (-logf(p + 1e-8f));
    g_cc[idx] = pos - neg;
}

// ---------------------------------------------------------------------------
// 3xTF32 mma.sync GEMM + fused norm partials.
// CTA tile 128(M) x 160(N) x 64(K). 512 threads, 16 warps = 4m x 4n.
// Warp tile 32x40: 2 m-frags x 5 n-frags, mma.m16n8k8.tf32, 3 passes.
// ---------------------------------------------------------------------------
#define SM_AH 0
#define SM_AL 8704              // 128*68
#define SM_BH 17408
#define SM_BL 28288             // + 160*68
#define SM_WORDS 39168          // 156,672 bytes

__device__ __forceinline__ void tf32_split(float f, uint32_t& h, uint32_t& l)
{
    asm("cvt.rna.tf32.f32 %0, %1;" : "=r"(h) : "f"(f));
    float r = f - __uint_as_float(h);
    asm("cvt.rna.tf32.f32 %0, %1;" : "=r"(l) : "f"(r));
}

#define MMA1688(d, a, b0, b1) \
    asm volatile("mma.sync.aligned.m16n8k8.row.col.f32.tf32.tf32.f32 " \
        "{%0,%1,%2,%3}, {%4,%5,%6,%7}, {%8,%9}, {%0,%1,%2,%3};" \
        : "+f"((d)[0]), "+f"((d)[1]), "+f"((d)[2]), "+f"((d)[3]) \
        : "r"((a)[0]), "r"((a)[1]), "r"((a)[2]), "r"((a)[3]), "r"(b0), "r"(b1))

__global__ void __launch_bounds__(512, 1) gemm_tf32(const float* __restrict__ A,
                                                     const float* __restrict__ Bm)
{
    extern __shared__ __align__(16) uint32_t sm[];

    const int tid = threadIdx.x;
    const int wid = tid >> 5, lane = tid & 31;
    const int wm = wid >> 2, wn = wid & 3;
    const int lr = lane >> 2, lc = lane & 3;

    const int row0 = blockIdx.x * 128;
    const int z = blockIdx.y;
    const int cbeg = (z * NCH) / SPLITS;
    const int cend = ((z + 1) * NCH) / SPLITS;

    const int r0 = tid >> 4;       // 0..31
    const int q  = tid & 15;       // 0..15 (float4 quad within 64-wide K)
    const bool doB = (blockIdx.x == 0);

    // producer register prefetch: A 4 float4/thread, B 5 float4/thread
    float4 pa[4], pb[5];
    {
        size_t kb = (size_t)cbeg * BKF;
        #pragma unroll
        for (int i = 0; i < 4; i++) {
            int garow = row0 + r0 + i * 32;
            pa[i] = (garow < BNR) ? *(const float4*)(A + (size_t)garow * HWD + kb + q * 4)
                                  : make_float4(0,0,0,0);
        }
        #pragma unroll
        for (int i = 0; i < 5; i++) {
            int gbrow = r0 + i * 32;
            pb[i] = *(const float4*)(Bm + (size_t)gbrow * HWD + kb + q * 4);
        }
    }

    float acc[2][5][4];
    #pragma unroll
    for (int f = 0; f < 2; f++)
        #pragma unroll
        for (int nf = 0; nf < 5; nf++)
            #pragma unroll
            for (int e = 0; e < 4; e++) acc[f][nf][e] = 0.f;

    float asq[4] = {0.f, 0.f, 0.f, 0.f};
    float bsq[5] = {0.f, 0.f, 0.f, 0.f, 0.f};

    for (int c = cbeg; c < cend; c++) {
        __syncthreads();
        // ---- convert + store tiles, accumulate norm partials
        #pragma unroll
        for (int i = 0; i < 4; i++) {
            float4 v = pa[i];
            asq[i] += v.x*v.x + v.y*v.y + v.z*v.z + v.w*v.w;
            uint4 hv, lv;
            tf32_split(v.x, hv.x, lv.x); tf32_split(v.y, hv.y, lv.y);
            tf32_split(v.z, hv.z, lv.z); tf32_split(v.w, hv.w, lv.w);
            int ar = r0 + i * 32;
            *(uint4*)(sm + SM_AH + ar * 68 + q * 4) = hv;
            *(uint4*)(sm + SM_AL + ar * 68 + q * 4) = lv;
        }
        #pragma unroll
        for (int i = 0; i < 5; i++) {
            float4 v = pb[i];
            bsq[i] += v.x*v.x + v.y*v.y + v.z*v.z + v.w*v.w;
            uint4 hv, lv;
            tf32_split(v.x, hv.x, lv.x); tf32_split(v.y, hv.y, lv.y);
            tf32_split(v.z, hv.z, lv.z); tf32_split(v.w, hv.w, lv.w);
            int br = r0 + i * 32;
            *(uint4*)(sm + SM_BH + br * 68 + q * 4) = hv;
            *(uint4*)(sm + SM_BL + br * 68 + q * 4) = lv;
        }
        __syncthreads();

        // ---- prefetch next chunk
        if (c + 1 < cend) {
            size_t kb = (size_t)(c + 1) * BKF;
            #pragma unroll
            for (int i = 0; i < 4; i++) {
                int garow = row0 + r0 + i * 32;
                pa[i] = (garow < BNR) ? *(const float4*)(A + (size_t)garow * HWD + kb + q * 4)
                                      : make_float4(0,0,0,0);
            }
            #pragma unroll
            for (int i = 0; i < 5; i++) {
                int gbrow = r0 + i * 32;
                pb[i] = *(const float4*)(Bm + (size_t)gbrow * HWD + kb + q * 4);
            }
        }

        // ---- compute: 8 k-steps of 8
        #pragma unroll
        for (int ks = 0; ks < 8; ks++) {
            int k0 = ks * 8;
            uint32_t ah[2][4], al[2][4];
            #pragma unroll
            for (int f = 0; f < 2; f++) {
                int m0 = wm * 32 + f * 16 + lr;
                ah[f][0] = sm[SM_AH + (m0    ) * 68 + k0 + lc];
                ah[f][1] = sm[SM_AH + (m0 + 8) * 68 + k0 + lc];
                ah[f][2] = sm[SM_AH + (m0    ) * 68 + k0 + lc + 4];
                ah[f][3] = sm[SM_AH + (m0 + 8) * 68 + k0 + lc + 4];
                al[f][0] = sm[SM_AL + (m0    ) * 68 + k0 + lc];
                al[f][1] = sm[SM_AL + (m0 + 8) * 68 + k0 + lc];
                al[f][2] = sm[SM_AL + (m0    ) * 68 + k0 + lc + 4];
                al[f][3] = sm[SM_AL + (m0 + 8) * 68 + k0 + lc + 4];
            }
            #pragma unroll
            for (int nf = 0; nf < 5; nf++) {
                int n0 = wn * 40 + nf * 8 + lr;
                uint32_t bh0 = sm[SM_BH + n0 * 68 + k0 + lc];
                uint32_t bh1 = sm[SM_BH + n0 * 68 + k0 + lc + 4];
                uint32_t bl0 = sm[SM_BL + n0 * 68 + k0 + lc];
                uint32_t bl1 = sm[SM_BL + n0 * 68 + k0 + lc + 4];
                #pragma unroll
                for (int f = 0; f < 2; f++) {
                    MMA1688(acc[f][nf], ah[f], bh0, bh1);
                    MMA1688(acc[f][nf], ah[f], bl0, bl1);
                    MMA1688(acc[f][nf], al[f], bh0, bh1);
                }
            }
        }
    }

    // ---- norm partial reduce: 16 consecutive threads share a row
    #pragma unroll
    for (int i = 0; i < 4; i++) {
        float s = asq[i];
        #pragma unroll
        for (int o = 8; o; o >>= 1) s += __shfl_down_sync(0xffffffffu, s, o, 16);
        if ((tid & 15) == 0) {
            int grow = row0 + r0 + i * 32;
            if (grow < BNR) g_pnp[z * BNR + grow] = s;
        }
    }
    if (doB) {
        #pragma unroll
        for (int i = 0; i < 5; i++) {
            float s = bsq[i];
            #pragma unroll
            for (int o = 8; o; o >>= 1) s += __shfl_down_sync(0xffffffffu, s, o, 16);
            if ((tid & 15) == 0) g_tnp[z * TT + r0 + i * 32] = s;
        }
    }

    // ---- epilogue: write dot-product partials
    #pragma unroll
    for (int f = 0; f < 2; f++) {
        int grow0 = row0 + wm * 32 + f * 16 + lr;
        #pragma unroll
        for (int nf = 0; nf < 5; nf++) {
            int col = wn * 40 + nf * 8 + lc * 2;
            if (grow0 < BNR) {
                float* o = g_part + ((size_t)z * BNR + grow0) * TT + col;
                o[0] = acc[f][nf][0]; o[1] = acc[f][nf][1];
            }
            if (grow0 + 8 < BNR) {
                float* o = g_part + ((size_t)z * BNR + grow0 + 8) * TT + col;
                o[0] = acc[f][nf][2]; o[1] = acc[f][nf][3];
            }
        }
    }
}

// ---------------------------------------------------------------------------
// Reduce norm partials (fixed order, deterministic)
// ---------------------------------------------------------------------------
__global__ void reduce_norms_kernel()
{
    int idx = blockIdx.x * blockDim.x + threadIdx.x;
    if (idx < BNR) {
        float s = 0.f;
        #pragma unroll
        for (int z = 0; z < SPLITS; z++) s += g_pnp[z * BNR + idx];
        g_pnorm[idx] = s;
    } else if (idx < BNR + TT) {
        int t = idx - BNR;
        float s = 0.f;
        #pragma unroll
        for (int z = 0; z < SPLITS; z++) s += g_tnp[z * TT + t];
        g_tnorm[t] = s;
    }
}

// ---------------------------------------------------------------------------
// Assemble C = 2 * dice_score + class_cost (fixed-order split-K reduce)
// ---------------------------------------------------------------------------
__global__ void assemble_kernel(const int* __restrict__ tgt_ids, float* __restrict__ out)
{
    int idx = blockIdx.x * blockDim.x + threadIdx.x;
    if (idx >= BNR*TT) return;
    int row = idx / TT, t = idx % TT;
    float dot = 0.f;
    #pragma unroll
    for (int s = 0; s < SPLITS; s++)
        dot += g_part[((size_t)s * BNR + row) * TT + t];
    float num = 2.f * dot;
    float den = g_pnorm[row] + g_tnorm[t];
    float score = -((num + 1e-4f) / (den + 1e-4f));
    float c = 2.f * score + g_cc[row * KCLS + tgt_ids[t]];
    if (!isfinite(c)) c = 0.f;
    out[idx] = c;
}

// ---------------------------------------------------------------------------
// Hungarian (Jonker-Volgenant), exact replica of reference _lsa.
// ---------------------------------------------------------------------------
__global__ void hungarian_kernel(const float* __restrict__ C, float* __restrict__ out)
{
    int b = blockIdx.x;
    int lane = threadIdx.x;

    __shared__ double cost[MT][NN];
    __shared__ double u[MT+1], v[NN+1], minv[NN+1];
    __shared__ int p[NN+1], way[NN+1], used[NN+1];

    for (int idx = lane; idx < MT*NN; idx += 32) {
        int r = idx / NN, c = idx % NN;
        cost[r][c] = (double)C[(size_t)(b*NN + c) * TT + b*MT + r];
    }
    for (int j = lane; j <= NN; j += 32) { v[j] = 0.0; p[j] = 0; way[j] = 0; }
    for (int j = lane; j <= MT; j += 32) u[j] = 0.0;
    __syncwarp();

    for (int i = 1; i <= MT; i++) {
        if (lane == 0) p[0] = i;
        for (int j = lane; j <= NN; j += 32) { minv[j] = 1e18; used[j] = 0; }
        __syncwarp();

        int j0 = 0;
        while (true) {
            if (lane == 0) used[j0] = 1;
            __syncwarp();
            int i0 = p[j0];
            double uu = u[i0];

            double bestv = 1e18;
            int bestj = NN + 1;
            for (int j = lane + 1; j <= NN; j += 32) {
                if (!used[j]) {
                    double cur = cost[i0-1][j-1] - uu - v[j];
                    if (cur < minv[j]) { minv[j] = cur; way[j] = j0; }
                    double mv = minv[j];
                    if (mv < bestv || (mv == bestv && j < bestj)) { bestv = mv; bestj = j; }
                }
            }
            for (int off = 16; off; off >>= 1) {
                double ov = __shfl_down_sync(0xffffffffu, bestv, off);
                int    oj = __shfl_down_sync(0xffffffffu, bestj, off);
                if (ov < bestv || (ov == bestv && oj < bestj)) { bestv = ov; bestj = oj; }
            }
            double delta = __shfl_sync(0xffffffffu, bestv, 0);
            int j1 = __shfl_sync(0xffffffffu, bestj, 0);
            __syncwarp();

            for (int j = lane; j <= NN; j += 32) {
                if (used[j]) { u[p[j]] += delta; v[j] -= delta; }
                else minv[j] -= delta;
            }
            __syncwarp();

            j0 = j1;
            if (p[j0] == 0) break;
            __syncwarp();
        }

        if (lane == 0) {
            int jj = j0;
            while (jj) { int jp = way[jj]; p[jj] = p[jp]; jj = jp; }
        }
        __syncwarp();
    }

    if (lane == 0) {
        int k = 0;
        for (int j = 1; j <= NN; j++) {
            if (p[j] != 0) {
                out[(size_t)BNR*TT + b*MT + k]            = (float)(j - 1);
                out[(size_t)BNR*TT + BB*MT + b*MT + k]    = (float)(p[j] - 1);
                k++;
            }
        }
    }
}

// ---------------------------------------------------------------------------
extern "C" void kernel_launch(void* const* d_in, const int* in_sizes, int n_in,
                              void* d_out, int out_size)
{
    const float* pred_masks   = (const float*)d_in[0];   // (8,100,160,160)
    const float* pred_logits  = (const float*)d_in[1];   // (8,100,80)
    const float* target_masks = (const float*)d_in[2];   // (160,160,160)
    const int*   tgt_ids      = (const int*)d_in[3];     // (160,)
    float* out = (float*)d_out;                           // C(128000) | rows(160) | cols(160)

    cudaFuncSetAttribute(gemm_tf32, cudaFuncAttributeMaxDynamicSharedMemorySize,
                         SM_WORDS * 4);

    class_kernel<<<(BNR*KCLS + 255)/256, 256>>>(pred_logits);

    gemm_tf32<<<dim3(7, SPLITS), 512, SM_WORDS * 4>>>(pred_masks, target_masks);

    reduce_norms_kernel<<<4, 256>>>();

    assemble_kernel<<<(BNR*TT + 255)/256, 256>>>(tgt_ids, out);

    hungarian_kernel<<<BB, 32>>>(out, out);
}

// round 6
// speedup vs baseline: 3.1100x; 1.0845x over previous
#include <cuda_runtime.h>
#include <math.h>
#include <stdint.h>

// Problem constants (fixed by setup_inputs)
#define BB 8
#define NN 100
#define HWD 25600
#define KCLS 80
#define TT 160
#define MT 20
#define BNR (BB*NN)            // 800

// GEMM config
#define SPLITS 21
#define BKF 32                 // fp32 K per chunk
#define NCH (HWD/BKF)          // 800 chunks total

// Scratch (allocation-free rule: __device__ globals)
__device__ float g_part[SPLITS*BNR*TT];   // split-K partial dot products
__device__ float g_pnp[SPLITS*BNR];       // per-split pred-norm partials
__device__ float g_tnp[SPLITS*TT];        // per-split target-norm partials
__device__ float g_pnorm[BNR];
__device__ float g_tnorm[TT];

// ---------------------------------------------------------------------------
// 3xTF32 mma.sync GEMM + fused norm partials, double-buffered smem.
// CTA tile 128(M) x 160(N) x 32(K). 512 threads, 16 warps = 4m x 4n.
// Warp tile 32x40: 2 m-frags x 5 n-frags, mma.m16n8k8.tf32, 3 passes.
// One __syncthreads per chunk; store next chunk into the other buffer
// while (other warps) compute the current one.
// ---------------------------------------------------------------------------
#define STG_WORDS 20736         // words per stage (82,944 B)
#define SM_AH 0
#define SM_AL 4608              // 128*36
#define SM_BH 9216
#define SM_BL 14976             // + 160*36
#define SMEM_BYTES (2*STG_WORDS*4)   // 165,888 B

__device__ __forceinline__ void tf32_split(float f, uint32_t& h, uint32_t& l)
{
    asm("cvt.rna.tf32.f32 %0, %1;" : "=r"(h) : "f"(f));
    float r = f - __uint_as_float(h);
    asm("cvt.rna.tf32.f32 %0, %1;" : "=r"(l) : "f"(r));
}

#define MMA1688(d, a, b0, b1) \
    asm volatile("mma.sync.aligned.m16n8k8.row.col.f32.tf32.tf32.f32 " \
        "{%0,%1,%2,%3}, {%4,%5,%6,%7}, {%8,%9}, {%0,%1,%2,%3};" \
        : "+f"((d)[0]), "+f"((d)[1]), "+f"((d)[2]), "+f"((d)[3]) \
        : "r"((a)[0]), "r"((a)[1]), "r"((a)[2]), "r"((a)[3]), "r"(b0), "r"(b1))

__global__ void __launch_bounds__(512, 1) gemm_tf32(const float* __restrict__ A,
                                                     const float* __restrict__ Bm)
{
    extern __shared__ __align__(16) uint32_t sm[];

    const int tid = threadIdx.x;
    const int wid = tid >> 5, lane = tid & 31;
    const int wm = wid >> 2, wn = wid & 3;
    const int lr = lane >> 2, lc = lane & 3;

    const int row0 = blockIdx.x * 128;
    const int z = blockIdx.y;
    const int cbeg = (z * NCH) / SPLITS;
    const int cend = ((z + 1) * NCH) / SPLITS;

    const int r8 = tid >> 3;       // 0..63
    const int q  = tid & 7;        // float4 quad within 32-wide K
    const bool bact3 = (tid < 256);
    const bool doB = (blockIdx.x == 0);

    float4 pa[2], pb[3];
    float asq[2] = {0.f, 0.f};
    float bsq[3] = {0.f, 0.f, 0.f};

    auto LDG = [&](int c) {
        size_t kb = (size_t)c * BKF;
        #pragma unroll
        for (int i = 0; i < 2; i++) {
            int gr = row0 + r8 + 64 * i;
            pa[i] = (gr < BNR) ? *(const float4*)(A + (size_t)gr * HWD + kb + q * 4)
                               : make_float4(0,0,0,0);
        }
        #pragma unroll
        for (int i = 0; i < 2; i++) {
            int gb = r8 + 64 * i;
            pb[i] = *(const float4*)(Bm + (size_t)gb * HWD + kb + q * 4);
        }
        pb[2] = bact3 ? *(const float4*)(Bm + (size_t)(r8 + 128) * HWD + kb + q * 4)
                      : make_float4(0,0,0,0);
    };

    auto CVTST = [&](int st) {
        uint32_t* s = sm + st * STG_WORDS;
        #pragma unroll
        for (int i = 0; i < 2; i++) {
            float4 v = pa[i];
            asq[i] += v.x*v.x + v.y*v.y + v.z*v.z + v.w*v.w;
            uint4 hv, lv;
            tf32_split(v.x, hv.x, lv.x); tf32_split(v.y, hv.y, lv.y);
            tf32_split(v.z, hv.z, lv.z); tf32_split(v.w, hv.w, lv.w);
            int ar = r8 + 64 * i;
            *(uint4*)(s + SM_AH + ar * 36 + q * 4) = hv;
            *(uint4*)(s + SM_AL + ar * 36 + q * 4) = lv;
        }
        #pragma unroll
        for (int i = 0; i < 3; i++) {
            if (i == 2 && !bact3) break;
            float4 v = pb[i];
            bsq[i] += v.x*v.x + v.y*v.y + v.z*v.z + v.w*v.w;
            uint4 hv, lv;
            tf32_split(v.x, hv.x, lv.x); tf32_split(v.y, hv.y, lv.y);
            tf32_split(v.z, hv.z, lv.z); tf32_split(v.w, hv.w, lv.w);
            int br = r8 + 64 * i;
            *(uint4*)(s + SM_BH + br * 36 + q * 4) = hv;
            *(uint4*)(s + SM_BL + br * 36 + q * 4) = lv;
        }
    };

    float acc[2][5][4];
    #pragma unroll
    for (int f = 0; f < 2; f++)
        #pragma unroll
        for (int nf = 0; nf < 5; nf++)
            #pragma unroll
            for (int e = 0; e < 4; e++) acc[f][nf][e] = 0.f;

    auto COMP = [&](int st) {
        uint32_t* s = sm + st * STG_WORDS;
        #pragma unroll
        for (int ks = 0; ks < 4; ks++) {
            int k0 = ks * 8;
            uint32_t ah[2][4], al[2][4];
            #pragma unroll
            for (int f = 0; f < 2; f++) {
                int m0 = wm * 32 + f * 16 + lr;
                ah[f][0] = s[SM_AH + (m0    ) * 36 + k0 + lc];
                ah[f][1] = s[SM_AH + (m0 + 8) * 36 + k0 + lc];
                ah[f][2] = s[SM_AH + (m0    ) * 36 + k0 + lc + 4];
                ah[f][3] = s[SM_AH + (m0 + 8) * 36 + k0 + lc + 4];
                al[f][0] = s[SM_AL + (m0    ) * 36 + k0 + lc];
                al[f][1] = s[SM_AL + (m0 + 8) * 36 + k0 + lc];
                al[f][2] = s[SM_AL + (m0    ) * 36 + k0 + lc + 4];
                al[f][3] = s[SM_AL + (m0 + 8) * 36 + k0 + lc + 4];
            }
            #pragma unroll
            for (int nf = 0; nf < 5; nf++) {
                int n0 = wn * 40 + nf * 8 + lr;
                uint32_t bh0 = s[SM_BH + n0 * 36 + k0 + lc];
                uint32_t bh1 = s[SM_BH + n0 * 36 + k0 + lc + 4];
                uint32_t bl0 = s[SM_BL + n0 * 36 + k0 + lc];
                uint32_t bl1 = s[SM_BL + n0 * 36 + k0 + lc + 4];
                #pragma unroll
                for (int f = 0; f < 2; f++) {
                    MMA1688(acc[f][nf], ah[f], bh0, bh1);
                    MMA1688(acc[f][nf], ah[f], bl0, bl1);
                    MMA1688(acc[f][nf], al[f], bh0, bh1);
                }
            }
        }
    };

    // pipeline: preload + store chunk cbeg into stage 0
    LDG(cbeg);
    CVTST(0);
    __syncthreads();

    for (int c = cbeg; c < cend; c++) {
        int st = (c - cbeg) & 1;
        bool more = (c + 1 < cend);
        if (more) LDG(c + 1);
        COMP(st);
        if (more) CVTST(st ^ 1);
        __syncthreads();
    }

    // ---- norm partial reduce: 8 consecutive threads share a row
    #pragma unroll
    for (int i = 0; i < 2; i++) {
        float sv = asq[i];
        #pragma unroll
        for (int o = 4; o; o >>= 1) sv += __shfl_down_sync(0xffffffffu, sv, o, 8);
        if (q == 0) {
            int gr = row0 + r8 + 64 * i;
            if (gr < BNR) g_pnp[z * BNR + gr] = sv;
        }
    }
    if (doB) {
        #pragma unroll
        for (int i = 0; i < 3; i++) {
            if (i == 2 && !bact3) break;
            float sv = bsq[i];
            #pragma unroll
            for (int o = 4; o; o >>= 1) sv += __shfl_down_sync(0xffffffffu, sv, o, 8);
            if (q == 0) g_tnp[z * TT + r8 + 64 * i] = sv;
        }
    }

    // ---- epilogue: write dot-product partials
    #pragma unroll
    for (int f = 0; f < 2; f++) {
        int grow0 = row0 + wm * 32 + f * 16 + lr;
        #pragma unroll
        for (int nf = 0; nf < 5; nf++) {
            int col = wn * 40 + nf * 8 + lc * 2;
            if (grow0 < BNR) {
                float* o = g_part + ((size_t)z * BNR + grow0) * TT + col;
                o[0] = acc[f][nf][0]; o[1] = acc[f][nf][1];
            }
            if (grow0 + 8 < BNR) {
                float* o = g_part + ((size_t)z * BNR + grow0 + 8) * TT + col;
                o[0] = acc[f][nf][2]; o[1] = acc[f][nf][3];
            }
        }
    }
}

// ---------------------------------------------------------------------------
// Reduce norm partials (fixed order, deterministic)
// ---------------------------------------------------------------------------
__global__ void reduce_norms_kernel()
{
    int idx = blockIdx.x * blockDim.x + threadIdx.x;
    if (idx < BNR) {
        float s = 0.f;
        #pragma unroll
        for (int z = 0; z < SPLITS; z++) s += g_pnp[z * BNR + idx];
        g_pnorm[idx] = s;
    } else if (idx < BNR + TT) {
        int t = idx - BNR;
        float s = 0.f;
        #pragma unroll
        for (int z = 0; z < SPLITS; z++) s += g_tnp[z * TT + t];
        g_tnorm[t] = s;
    }
}

// ---------------------------------------------------------------------------
// Assemble C = 2 * dice_score + focal class cost (computed inline).
// Fixed-order split-K reduce -> deterministic.
// ---------------------------------------------------------------------------
__global__ void assemble_kernel(const float* __restrict__ logits,
                                const int* __restrict__ tgt_ids,
                                float* __restrict__ out)
{
    int idx = blockIdx.x * blockDim.x + threadIdx.x;
    if (idx >= BNR*TT) return;
    int row = idx / TT, t = idx % TT;
    float dot = 0.f;
    #pragma unroll
    for (int s = 0; s < SPLITS; s++)
        dot += g_part[((size_t)s * BNR + row) * TT + t];
    float den = g_pnorm[row] + g_tnorm[t];
    float score = -((2.f * dot + 1e-4f) / (den + 1e-4f));

    float x = logits[row * KCLS + tgt_ids[t]];
    float pp = 1.f / (1.f + expf(-x));
    float neg = 0.75f * pp * pp * (-logf(1.f - pp + 1e-8f));
    float pos = 0.25f * (1.f - pp) * (1.f - pp) * (-logf(pp + 1e-8f));

    float c = 2.f * score + (pos - neg);
    if (!isfinite(c)) c = 0.f;
    out[idx] = c;
}

// ---------------------------------------------------------------------------
// Hungarian (Jonker-Volgenant), exact replica of reference _lsa.
// Register-resident minv/used/v (each lane owns 4 columns); cost/u/p/way
// in shared. Same arithmetic order + tie-breaks as the numpy reference.
// ---------------------------------------------------------------------------
__global__ void hungarian_kernel(const float* __restrict__ C, float* __restrict__ out)
{
    int b = blockIdx.x;
    int lane = threadIdx.x;

    __shared__ double cost[MT][NN];
    __shared__ double u[MT+1];
    __shared__ int p[NN+1], way[NN+1];

    for (int idx = lane; idx < MT*NN; idx += 32) {
        int r = idx / NN, c = idx % NN;
        cost[r][c] = (double)C[(size_t)(b*NN + c) * TT + b*MT + r];
    }
    for (int j = lane; j <= NN; j += 32) { p[j] = 0; way[j] = 0; }
    for (int j = lane; j <= MT; j += 32) u[j] = 0.0;
    double vreg[4] = {0.0, 0.0, 0.0, 0.0};
    __syncwarp();

    for (int i = 1; i <= MT; i++) {
        if (lane == 0) p[0] = i;
        double minv[4] = {1e18, 1e18, 1e18, 1e18};
        int usedm = 0;
        bool used0 = false;
        int j0 = 0;
        __syncwarp();

        while (true) {
            if (j0 == 0) used0 = true;                       // same in all lanes
            else { int ol = (j0-1) & 31, ok = (j0-1) >> 5;
                   if (lane == ol) usedm |= 1 << ok; }
            int i0 = p[j0];
            double uu = u[i0];

            double bestv = 1e18;
            int bestj = NN + 1;
            #pragma unroll
            for (int kk = 0; kk < 4; kk++) {
                int j = lane + 1 + 32 * kk;
                if (j <= NN && !((usedm >> kk) & 1)) {
                    double cur = cost[i0-1][j-1] - uu - vreg[kk];
                    if (cur < minv[kk]) { minv[kk] = cur; way[j] = j0; }
                    if (minv[kk] < bestv) { bestv = minv[kk]; bestj = j; }
                }
            }
            #pragma unroll
            for (int off = 16; off; off >>= 1) {
                double ov = __shfl_down_sync(0xffffffffu, bestv, off);
                int    oj = __shfl_down_sync(0xffffffffu, bestj, off);
                if (ov < bestv || (ov == bestv && oj < bestj)) { bestv = ov; bestj = oj; }
            }
            double delta = __shfl_sync(0xffffffffu, bestv, 0);
            int j1 = __shfl_sync(0xffffffffu, bestj, 0);

            if (lane == 0 && used0) u[i] += delta;           // p[0] == i
            #pragma unroll
            for (int kk = 0; kk < 4; kk++) {
                int j = lane + 1 + 32 * kk;
                if (j <= NN) {
                    if ((usedm >> kk) & 1) { u[p[j]] += delta; vreg[kk] -= delta; }
                    else minv[kk] -= delta;
                }
            }
            __syncwarp();

            j0 = j1;
            if (p[j0] == 0) break;
        }

        if (lane == 0) {   // augment along way[] chain
            int jj = j0;
            while (jj) { int jp = way[jj]; p[jj] = p[jp]; jj = jp; }
        }
        __syncwarp();
    }

    if (lane == 0) {
        int k = 0;
        for (int j = 1; j <= NN; j++) {
            if (p[j] != 0) {
                out[(size_t)BNR*TT + b*MT + k]            = (float)(j - 1);
                out[(size_t)BNR*TT + BB*MT + b*MT + k]    = (float)(p[j] - 1);
                k++;
            }
        }
    }
}

// ---------------------------------------------------------------------------
extern "C" void kernel_launch(void* const* d_in, const int* in_sizes, int n_in,
                              void* d_out, int out_size)
{
    const float* pred_masks   = (const float*)d_in[0];   // (8,100,160,160)
    const float* pred_logits  = (const float*)d_in[1];   // (8,100,80)
    const float* target_masks = (const float*)d_in[2];   // (160,160,160)
    const int*   tgt_ids      = (const int*)d_in[3];     // (160,)
    float* out = (float*)d_out;                           // C(128000) | rows(160) | cols(160)

    cudaFuncSetAttribute(gemm_tf32, cudaFuncAttributeMaxDynamicSharedMemorySize,
                         SMEM_BYTES);

    gemm_tf32<<<dim3(7, SPLITS), 512, SMEM_BYTES>>>(pred_masks, target_masks);

    reduce_norms_kernel<<<4, 256>>>();

    assemble_kernel<<<(BNR*TT + 255)/256, 256>>>(pred_logits, tgt_ids, out);

    hungarian_kernel<<<BB, 32>>>(out, out);
}

// round 8
// speedup vs baseline: 3.1868x; 1.0247x over previous
#include <cuda_runtime.h>
#include <math.h>
#include <stdint.h>

// Problem constants (fixed by setup_inputs)
#define BB 8
#define NN 100
#define HWD 25600
#define KCLS 80
#define TT 160
#define MT 20
#define BNR (BB*NN)            // 800

// GEMM config
#define SPLITS 21
#define BKF 32                 // fp32 K per chunk
#define NCH (HWD/BKF)          // 800 chunks total

// Scratch (allocation-free rule: __device__ globals)
__device__ float g_part[SPLITS*BNR*TT];   // split-K partial dot products
__device__ float g_pnp[SPLITS*BNR];       // per-split pred-norm partials
__device__ float g_tnp[SPLITS*TT];        // per-split target-norm partials
__device__ float g_pnorm[BNR];
__device__ float g_tnorm[TT];

// ---------------------------------------------------------------------------
// 3xTF32 mma.sync GEMM + fused norm partials, double-buffered smem.
// CTA tile 128(M) x 160(N) x 32(K). 512 threads, 16 warps = 4m x 4n.
// ---------------------------------------------------------------------------
#define STG_WORDS 20736         // words per stage (82,944 B)
#define SM_AH 0
#define SM_AL 4608              // 128*36
#define SM_BH 9216
#define SM_BL 14976             // + 160*36
#define SMEM_BYTES (2*STG_WORDS*4)   // 165,888 B

__device__ __forceinline__ void tf32_split(float f, uint32_t& h, uint32_t& l)
{
    asm("cvt.rna.tf32.f32 %0, %1;" : "=r"(h) : "f"(f));
    float r = f - __uint_as_float(h);
    asm("cvt.rna.tf32.f32 %0, %1;" : "=r"(l) : "f"(r));
}

#define MMA1688(d, a, b0, b1) \
    asm volatile("mma.sync.aligned.m16n8k8.row.col.f32.tf32.tf32.f32 " \
        "{%0,%1,%2,%3}, {%4,%5,%6,%7}, {%8,%9}, {%0,%1,%2,%3};" \
        : "+f"((d)[0]), "+f"((d)[1]), "+f"((d)[2]), "+f"((d)[3]) \
        : "r"((a)[0]), "r"((a)[1]), "r"((a)[2]), "r"((a)[3]), "r"(b0), "r"(b1))

__global__ void __launch_bounds__(512, 1) gemm_tf32(const float* __restrict__ A,
                                                     const float* __restrict__ Bm)
{
    extern __shared__ __align__(16) uint32_t sm[];

    const int tid = threadIdx.x;
    const int wid = tid >> 5, lane = tid & 31;
    const int wm = wid >> 2, wn = wid & 3;
    const int lr = lane >> 2, lc = lane & 3;

    const int row0 = blockIdx.x * 128;
    const int z = blockIdx.y;
    const int cbeg = (z * NCH) / SPLITS;
    const int cend = ((z + 1) * NCH) / SPLITS;

    const int r8 = tid >> 3;       // 0..63
    const int q  = tid & 7;        // float4 quad within 32-wide K
    const bool bact3 = (tid < 256);
    const bool doB = (blockIdx.x == 0);

    float4 pa[2], pb[3];
    float asq[2] = {0.f, 0.f};
    float bsq[3] = {0.f, 0.f, 0.f};

    auto LDG = [&](int c) {
        size_t kb = (size_t)c * BKF;
        #pragma unroll
        for (int i = 0; i < 2; i++) {
            int gr = row0 + r8 + 64 * i;
            pa[i] = (gr < BNR) ? *(const float4*)(A + (size_t)gr * HWD + kb + q * 4)
                               : make_float4(0,0,0,0);
        }
        #pragma unroll
        for (int i = 0; i < 2; i++) {
            int gb = r8 + 64 * i;
            pb[i] = *(const float4*)(Bm + (size_t)gb * HWD + kb + q * 4);
        }
        pb[2] = bact3 ? *(const float4*)(Bm + (size_t)(r8 + 128) * HWD + kb + q * 4)
                      : make_float4(0,0,0,0);
    };

    auto CVTST = [&](int st) {
        uint32_t* s = sm + st * STG_WORDS;
        #pragma unroll
        for (int i = 0; i < 2; i++) {
            float4 v = pa[i];
            asq[i] += v.x*v.x + v.y*v.y + v.z*v.z + v.w*v.w;
            uint4 hv, lv;
            tf32_split(v.x, hv.x, lv.x); tf32_split(v.y, hv.y, lv.y);
            tf32_split(v.z, hv.z, lv.z); tf32_split(v.w, hv.w, lv.w);
            int ar = r8 + 64 * i;
            *(uint4*)(s + SM_AH + ar * 36 + q * 4) = hv;
            *(uint4*)(s + SM_AL + ar * 36 + q * 4) = lv;
        }
        #pragma unroll
        for (int i = 0; i < 3; i++) {
            if (i == 2 && !bact3) break;
            float4 v = pb[i];
            bsq[i] += v.x*v.x + v.y*v.y + v.z*v.z + v.w*v.w;
            uint4 hv, lv;
            tf32_split(v.x, hv.x, lv.x); tf32_split(v.y, hv.y, lv.y);
            tf32_split(v.z, hv.z, lv.z); tf32_split(v.w, hv.w, lv.w);
            int br = r8 + 64 * i;
            *(uint4*)(s + SM_BH + br * 36 + q * 4) = hv;
            *(uint4*)(s + SM_BL + br * 36 + q * 4) = lv;
        }
    };

    float acc[2][5][4];
    #pragma unroll
    for (int f = 0; f < 2; f++)
        #pragma unroll
        for (int nf = 0; nf < 5; nf++)
            #pragma unroll
            for (int e = 0; e < 4; e++) acc[f][nf][e] = 0.f;

    auto COMP = [&](int st) {
        uint32_t* s = sm + st * STG_WORDS;
        #pragma unroll
        for (int ks = 0; ks < 4; ks++) {
            int k0 = ks * 8;
            uint32_t ah[2][4], al[2][4];
            #pragma unroll
            for (int f = 0; f < 2; f++) {
                int m0 = wm * 32 + f * 16 + lr;
                ah[f][0] = s[SM_AH + (m0    ) * 36 + k0 + lc];
                ah[f][1] = s[SM_AH + (m0 + 8) * 36 + k0 + lc];
                ah[f][2] = s[SM_AH + (m0    ) * 36 + k0 + lc + 4];
                ah[f][3] = s[SM_AH + (m0 + 8) * 36 + k0 + lc + 4];
                al[f][0] = s[SM_AL + (m0    ) * 36 + k0 + lc];
                al[f][1] = s[SM_AL + (m0 + 8) * 36 + k0 + lc];
                al[f][2] = s[SM_AL + (m0    ) * 36 + k0 + lc + 4];
                al[f][3] = s[SM_AL + (m0 + 8) * 36 + k0 + lc + 4];
            }
            #pragma unroll
            for (int nf = 0; nf < 5; nf++) {
                int n0 = wn * 40 + nf * 8 + lr;
                uint32_t bh0 = s[SM_BH + n0 * 36 + k0 + lc];
                uint32_t bh1 = s[SM_BH + n0 * 36 + k0 + lc + 4];
                uint32_t bl0 = s[SM_BL + n0 * 36 + k0 + lc];
                uint32_t bl1 = s[SM_BL + n0 * 36 + k0 + lc + 4];
                #pragma unroll
                for (int f = 0; f < 2; f++) {
                    MMA1688(acc[f][nf], ah[f], bh0, bh1);
                    MMA1688(acc[f][nf], ah[f], bl0, bl1);
                    MMA1688(acc[f][nf], al[f], bh0, bh1);
                }
            }
        }
    };

    LDG(cbeg);
    CVTST(0);
    __syncthreads();

    for (int c = cbeg; c < cend; c++) {
        int st = (c - cbeg) & 1;
        bool more = (c + 1 < cend);
        if (more) LDG(c + 1);
        COMP(st);
        if (more) CVTST(st ^ 1);
        __syncthreads();
    }

    #pragma unroll
    for (int i = 0; i < 2; i++) {
        float sv = asq[i];
        #pragma unroll
        for (int o = 4; o; o >>= 1) sv += __shfl_down_sync(0xffffffffu, sv, o, 8);
        if (q == 0) {
            int gr = row0 + r8 + 64 * i;
            if (gr < BNR) g_pnp[z * BNR + gr] = sv;
        }
    }
    if (doB) {
        #pragma unroll
        for (int i = 0; i < 3; i++) {
            if (i == 2 && !bact3) break;
            float sv = bsq[i];
            #pragma unroll
            for (int o = 4; o; o >>= 1) sv += __shfl_down_sync(0xffffffffu, sv, o, 8);
            if (q == 0) g_tnp[z * TT + r8 + 64 * i] = sv;
        }
    }

    #pragma unroll
    for (int f = 0; f < 2; f++) {
        int grow0 = row0 + wm * 32 + f * 16 + lr;
        #pragma unroll
        for (int nf = 0; nf < 5; nf++) {
            int col = wn * 40 + nf * 8 + lc * 2;
            if (grow0 < BNR) {
                float* o = g_part + ((size_t)z * BNR + grow0) * TT + col;
                o[0] = acc[f][nf][0]; o[1] = acc[f][nf][1];
            }
            if (grow0 + 8 < BNR) {
                float* o = g_part + ((size_t)z * BNR + grow0 + 8) * TT + col;
                o[0] = acc[f][nf][2]; o[1] = acc[f][nf][3];
            }
        }
    }
}

// ---------------------------------------------------------------------------
// Reduce norm partials (fixed order, deterministic)
// ---------------------------------------------------------------------------
__global__ void reduce_norms_kernel()
{
    int idx = blockIdx.x * blockDim.x + threadIdx.x;
    if (idx < BNR) {
        float s = 0.f;
        #pragma unroll
        for (int z = 0; z < SPLITS; z++) s += g_pnp[z * BNR + idx];
        g_pnorm[idx] = s;
    } else if (idx < BNR + TT) {
        int t = idx - BNR;
        float s = 0.f;
        #pragma unroll
        for (int z = 0; z < SPLITS; z++) s += g_tnp[z * TT + t];
        g_tnorm[t] = s;
    }
}

// ---------------------------------------------------------------------------
// Assemble C = 2 * dice_score + focal class cost (inline), float4-vectorized.
// Fixed-order split-K reduce -> deterministic.
// ---------------------------------------------------------------------------
__global__ void assemble_kernel(const float* __restrict__ logits,
                                const int* __restrict__ tgt_ids,
                                float* __restrict__ out)
{
    int idx = blockIdx.x * blockDim.x + threadIdx.x;
    if (idx >= BNR*TT/4) return;
    int row = idx / (TT/4), t4 = idx % (TT/4);

    float4 dot = make_float4(0.f, 0.f, 0.f, 0.f);
    #pragma unroll
    for (int s = 0; s < SPLITS; s++) {
        float4 v = *(const float4*)(g_part + ((size_t)s * BNR + row) * TT + t4 * 4);
        dot.x += v.x; dot.y += v.y; dot.z += v.z; dot.w += v.w;
    }
    float pn = g_pnorm[row];
    const float* lrow = logits + row * KCLS;

    float4 res;
    float* dp = (float*)&dot;
    float* rp = (float*)&res;
    #pragma unroll
    for (int e = 0; e < 4; e++) {
        int t = t4 * 4 + e;
        float den = pn + g_tnorm[t];
        float score = -((2.f * dp[e] + 1e-4f) / (den + 1e-4f));
        float x = lrow[tgt_ids[t]];
        float pp = 1.f / (1.f + expf(-x));
        float neg = 0.75f * pp * pp * (-logf(1.f - pp + 1e-8f));
        float pos = 0.25f * (1.f - pp) * (1.f - pp) * (-logf(pp + 1e-8f));
        float c = 2.f * score + (pos - neg);
        if (!isfinite(c)) c = 0.f;
        rp[e] = c;
    }
    *(float4*)(out + (size_t)row * TT + t4 * 4) = res;
}

// ---------------------------------------------------------------------------
// Hungarian (Jonker-Volgenant) — absolute-distance reformulation.
// Selection order provably identical to the reference (uniform-shift
// invariance); per-iteration u/v/minv sweeps eliminated; all comparisons via
// monotone double->uint64 keys (integer pipe); butterfly argmin; first-index
// tie-breaks preserved exactly.
// ---------------------------------------------------------------------------
__device__ __forceinline__ unsigned long long d2k(double x)
{
    long long b = __double_as_longlong(x);
    return (unsigned long long)b ^
           ((b < 0) ? 0xFFFFFFFFFFFFFFFFULL : 0x8000000000000000ULL);
}
__device__ __forceinline__ double k2d(unsigned long long k)
{
    unsigned long long b = k ^
        (((long long)k < 0) ? 0x8000000000000000ULL : 0xFFFFFFFFFFFFFFFFULL);
    return __longlong_as_double((long long)b);
}

__global__ void hungarian_kernel(const float* __restrict__ C, float* __restrict__ out)
{
    int b = blockIdx.x;
    int lane = threadIdx.x;

    __shared__ double cost[MT][NN];
    __shared__ double u[MT+1];
    __shared__ int p[NN+1], way[NN+1];

    for (int idx = lane; idx < MT*NN; idx += 32) {
        int r = idx / NN, c = idx % NN;
        cost[r][c] = (double)C[(size_t)(b*NN + c) * TT + b*MT + r];
    }
    for (int j = lane; j <= NN; j += 32) { p[j] = 0; way[j] = 0; }
    for (int j = lane; j <= MT; j += 32) u[j] = 0.0;
    double v[4] = {0.0, 0.0, 0.0, 0.0};
    const int jcol[4] = {lane + 1, lane + 33, lane + 65, lane + 97};
    const unsigned long long KINF = d2k(1e18);
    __syncwarp();

    for (int i = 1; i <= MT; i++) {
        unsigned long long absk[4] = {KINF, KINF, KINF, KINF};
        double dj[4] = {0.0, 0.0, 0.0, 0.0};
        int usedm = (lane >= 4) ? 8 : 0;       // kk=3 invalid for lane>=4 (j>100)
        double Dprev = 0.0;
        int j0 = 0, i0 = i;

        while (true) {
            // mark previously selected column as used; record its join-S
            if (j0 > 0) {
                int ol = (j0 - 1) & 31, ok = (j0 - 1) >> 5;
                if (lane == ol) {
                    #pragma unroll
                    for (int kk = 0; kk < 4; kk++)
                        if (kk == ok) { usedm |= 1 << kk; dj[kk] = Dprev; }
                }
            }
            double off = Dprev - u[i0];

            // relax unused columns: abs[j] = min(abs[j], cost - u0 - v0 + S_prev)
            #pragma unroll
            for (int kk = 0; kk < 4; kk++) {
                if (!((usedm >> kk) & 1)) {
                    double cur = (cost[i0 - 1][jcol[kk] - 1] - v[kk]) + off;
                    unsigned long long ck = d2k(cur);
                    if (ck < absk[kk]) { absk[kk] = ck; way[jcol[kk]] = j0; }
                }
            }

            // argmin over unused (key, j) — lane-local (kk ascending = j ascending,
            // strict < keeps the first) then 5-level butterfly
            unsigned long long bk = 0xFFFFFFFFFFFFFFFFULL;
            int bj = NN + 2;
            #pragma unroll
            for (int kk = 0; kk < 4; kk++) {
                if (!((usedm >> kk) & 1) && absk[kk] < bk) { bk = absk[kk]; bj = jcol[kk]; }
            }
            #pragma unroll
            for (int o = 16; o; o >>= 1) {
                unsigned long long ok2 = __shfl_xor_sync(0xffffffffu, bk, o);
                int oj2 = __shfl_xor_sync(0xffffffffu, bj, o);
                if (ok2 < bk || (ok2 == bk && oj2 < bj)) { bk = ok2; bj = oj2; }
            }
            Dprev = k2d(bk);            // S_k = abs[j1]
            j0 = bj;
            i0 = p[j0];
            if (i0 == 0) break;
        }

        double Slast = Dprev;
        // deferred potential updates (match reference's end-of-search u/v)
        if (lane == 0) u[i] += Slast;
        #pragma unroll
        for (int kk = 0; kk < 4; kk++) {
            if (((usedm >> kk) & 1) && !(kk == 3 && lane >= 4)) {
                double du = Slast - dj[kk];
                int r = p[jcol[kk]];       // distinct rows across lanes
                u[r] += du;
                v[kk] -= du;
            }
        }
        __syncwarp();
        if (lane == 0) {                  // augment along way[] chain
            p[0] = i;
            int jj = j0;
            while (jj) { int jp = way[jj]; p[jj] = p[jp]; jj = jp; }
        }
        __syncwarp();
    }

    if (lane == 0) {
        int k = 0;
        for (int j = 1; j <= NN; j++) {
            if (p[j] != 0) {
                out[(size_t)BNR*TT + b*MT + k]            = (float)(j - 1);
                out[(size_t)BNR*TT + BB*MT + b*MT + k]    = (float)(p[j] - 1);
                k++;
            }
        }
    }
}

// ---------------------------------------------------------------------------
extern "C" void kernel_launch(void* const* d_in, const int* in_sizes, int n_in,
                              void* d_out, int out_size)
{
    const float* pred_masks   = (const float*)d_in[0];   // (8,100,160,160)
    const float* pred_logits  = (const float*)d_in[1];   // (8,100,80)
    const float* target_masks = (const float*)d_in[2];   // (160,160,160)
    const int*   tgt_ids      = (const int*)d_in[3];     // (160,)
    float* out = (float*)d_out;                           // C(128000) | rows(160) | cols(160)

    cudaFuncSetAttribute(gemm_tf32, cudaFuncAttributeMaxDynamicSharedMemorySize,
                         SMEM_BYTES);

    gemm_tf32<<<dim3(7, SPLITS), 512, SMEM_BYTES>>>(pred_masks, target_masks);

    reduce_norms_kernel<<<4, 256>>>();

    assemble_kernel<<<(BNR*TT/4 + 255)/256, 256>>>(pred_logits, tgt_ids, out);

    hungarian_kernel<<<BB, 32>>>(out, out);
}

// round 9
// speedup vs baseline: 3.3087x; 1.0383x over previous
#include <cuda_runtime.h>
#include <math.h>
#include <stdint.h>

// Problem constants (fixed by setup_inputs)
#define BB 8
#define NN 100
#define HWD 25600
#define KCLS 80
#define TT 160
#define MT 20
#define BNR (BB*NN)            // 800

// GEMM config
#define SPLITS 21
#define BKF 32                 // fp32 K per chunk
#define NCH (HWD/BKF)          // 800 chunks total

// Scratch (allocation-free rule: __device__ globals)
__device__ float g_part[SPLITS*BNR*TT];   // split-K partial dot products
__device__ float g_pnp[SPLITS*BNR];       // per-split pred-norm partials
__device__ float g_tnp[SPLITS*TT];        // per-split target-norm partials
__device__ float g_pnorm[BNR];
__device__ float g_tnorm[TT];

// ---------------------------------------------------------------------------
// 3xTF32 mma.sync GEMM + fused norm partials, double-buffered smem.
// CTA tile 128(M) x 160(N) x 32(K). 512 threads, 16 warps = 4m x 4n.
// ---------------------------------------------------------------------------
#define STG_WORDS 20736         // words per stage (82,944 B)
#define SM_AH 0
#define SM_AL 4608              // 128*36
#define SM_BH 9216
#define SM_BL 14976             // + 160*36
#define SMEM_BYTES (2*STG_WORDS*4)   // 165,888 B

__device__ __forceinline__ void tf32_split(float f, uint32_t& h, uint32_t& l)
{
    asm("cvt.rna.tf32.f32 %0, %1;" : "=r"(h) : "f"(f));
    float r = f - __uint_as_float(h);
    asm("cvt.rna.tf32.f32 %0, %1;" : "=r"(l) : "f"(r));
}

#define MMA1688(d, a, b0, b1) \
    asm volatile("mma.sync.aligned.m16n8k8.row.col.f32.tf32.tf32.f32 " \
        "{%0,%1,%2,%3}, {%4,%5,%6,%7}, {%8,%9}, {%0,%1,%2,%3};" \
        : "+f"((d)[0]), "+f"((d)[1]), "+f"((d)[2]), "+f"((d)[3]) \
        : "r"((a)[0]), "r"((a)[1]), "r"((a)[2]), "r"((a)[3]), "r"(b0), "r"(b1))

__global__ void __launch_bounds__(512, 1) gemm_tf32(const float* __restrict__ A,
                                                     const float* __restrict__ Bm)
{
    extern __shared__ __align__(16) uint32_t sm[];

    const int tid = threadIdx.x;
    const int wid = tid >> 5, lane = tid & 31;
    const int wm = wid >> 2, wn = wid & 3;
    const int lr = lane >> 2, lc = lane & 3;

    const int row0 = blockIdx.x * 128;
    const int z = blockIdx.y;
    const int cbeg = (z * NCH) / SPLITS;
    const int cend = ((z + 1) * NCH) / SPLITS;

    const int r8 = tid >> 3;       // 0..63
    const int q  = tid & 7;        // float4 quad within 32-wide K
    const bool bact3 = (tid < 256);
    const bool doB = (blockIdx.x == 0);

    float4 pa[2], pb[3];
    float asq[2] = {0.f, 0.f};
    float bsq[3] = {0.f, 0.f, 0.f};

    auto LDG = [&](int c) {
        size_t kb = (size_t)c * BKF;
        #pragma unroll
        for (int i = 0; i < 2; i++) {
            int gr = row0 + r8 + 64 * i;
            pa[i] = (gr < BNR) ? *(const float4*)(A + (size_t)gr * HWD + kb + q * 4)
                               : make_float4(0,0,0,0);
        }
        #pragma unroll
        for (int i = 0; i < 2; i++) {
            int gb = r8 + 64 * i;
            pb[i] = *(const float4*)(Bm + (size_t)gb * HWD + kb + q * 4);
        }
        pb[2] = bact3 ? *(const float4*)(Bm + (size_t)(r8 + 128) * HWD + kb + q * 4)
                      : make_float4(0,0,0,0);
    };

    auto CVTST = [&](int st) {
        uint32_t* s = sm + st * STG_WORDS;
        #pragma unroll
        for (int i = 0; i < 2; i++) {
            float4 v = pa[i];
            asq[i] += v.x*v.x + v.y*v.y + v.z*v.z + v.w*v.w;
            uint4 hv, lv;
            tf32_split(v.x, hv.x, lv.x); tf32_split(v.y, hv.y, lv.y);
            tf32_split(v.z, hv.z, lv.z); tf32_split(v.w, hv.w, lv.w);
            int ar = r8 + 64 * i;
            *(uint4*)(s + SM_AH + ar * 36 + q * 4) = hv;
            *(uint4*)(s + SM_AL + ar * 36 + q * 4) = lv;
        }
        #pragma unroll
        for (int i = 0; i < 3; i++) {
            if (i == 2 && !bact3) break;
            float4 v = pb[i];
            bsq[i] += v.x*v.x + v.y*v.y + v.z*v.z + v.w*v.w;
            uint4 hv, lv;
            tf32_split(v.x, hv.x, lv.x); tf32_split(v.y, hv.y, lv.y);
            tf32_split(v.z, hv.z, lv.z); tf32_split(v.w, hv.w, lv.w);
            int br = r8 + 64 * i;
            *(uint4*)(s + SM_BH + br * 36 + q * 4) = hv;
            *(uint4*)(s + SM_BL + br * 36 + q * 4) = lv;
        }
    };

    float acc[2][5][4];
    #pragma unroll
    for (int f = 0; f < 2; f++)
        #pragma unroll
        for (int nf = 0; nf < 5; nf++)
            #pragma unroll
            for (int e = 0; e < 4; e++) acc[f][nf][e] = 0.f;

    auto COMP = [&](int st) {
        uint32_t* s = sm + st * STG_WORDS;
        #pragma unroll
        for (int ks = 0; ks < 4; ks++) {
            int k0 = ks * 8;
            uint32_t ah[2][4], al[2][4];
            #pragma unroll
            for (int f = 0; f < 2; f++) {
                int m0 = wm * 32 + f * 16 + lr;
                ah[f][0] = s[SM_AH + (m0    ) * 36 + k0 + lc];
                ah[f][1] = s[SM_AH + (m0 + 8) * 36 + k0 + lc];
                ah[f][2] = s[SM_AH + (m0    ) * 36 + k0 + lc + 4];
                ah[f][3] = s[SM_AH + (m0 + 8) * 36 + k0 + lc + 4];
                al[f][0] = s[SM_AL + (m0    ) * 36 + k0 + lc];
                al[f][1] = s[SM_AL + (m0 + 8) * 36 + k0 + lc];
                al[f][2] = s[SM_AL + (m0    ) * 36 + k0 + lc + 4];
                al[f][3] = s[SM_AL + (m0 + 8) * 36 + k0 + lc + 4];
            }
            #pragma unroll
            for (int nf = 0; nf < 5; nf++) {
                int n0 = wn * 40 + nf * 8 + lr;
                uint32_t bh0 = s[SM_BH + n0 * 36 + k0 + lc];
                uint32_t bh1 = s[SM_BH + n0 * 36 + k0 + lc + 4];
                uint32_t bl0 = s[SM_BL + n0 * 36 + k0 + lc];
                uint32_t bl1 = s[SM_BL + n0 * 36 + k0 + lc + 4];
                #pragma unroll
                for (int f = 0; f < 2; f++) {
                    MMA1688(acc[f][nf], ah[f], bh0, bh1);
                    MMA1688(acc[f][nf], ah[f], bl0, bl1);
                    MMA1688(acc[f][nf], al[f], bh0, bh1);
                }
            }
        }
    };

    LDG(cbeg);
    CVTST(0);
    __syncthreads();

    for (int c = cbeg; c < cend; c++) {
        int st = (c - cbeg) & 1;
        bool more = (c + 1 < cend);
        if (more) LDG(c + 1);
        COMP(st);
        if (more) CVTST(st ^ 1);
        __syncthreads();
    }

    #pragma unroll
    for (int i = 0; i < 2; i++) {
        float sv = asq[i];
        #pragma unroll
        for (int o = 4; o; o >>= 1) sv += __shfl_down_sync(0xffffffffu, sv, o, 8);
        if (q == 0) {
            int gr = row0 + r8 + 64 * i;
            if (gr < BNR) g_pnp[z * BNR + gr] = sv;
        }
    }
    if (doB) {
        #pragma unroll
        for (int i = 0; i < 3; i++) {
            if (i == 2 && !bact3) break;
            float sv = bsq[i];
            #pragma unroll
            for (int o = 4; o; o >>= 1) sv += __shfl_down_sync(0xffffffffu, sv, o, 8);
            if (q == 0) g_tnp[z * TT + r8 + 64 * i] = sv;
        }
    }

    #pragma unroll
    for (int f = 0; f < 2; f++) {
        int grow0 = row0 + wm * 32 + f * 16 + lr;
        #pragma unroll
        for (int nf = 0; nf < 5; nf++) {
            int col = wn * 40 + nf * 8 + lc * 2;
            if (grow0 < BNR) {
                float* o = g_part + ((size_t)z * BNR + grow0) * TT + col;
                o[0] = acc[f][nf][0]; o[1] = acc[f][nf][1];
            }
            if (grow0 + 8 < BNR) {
                float* o = g_part + ((size_t)z * BNR + grow0 + 8) * TT + col;
                o[0] = acc[f][nf][2]; o[1] = acc[f][nf][3];
            }
        }
    }
}

// ---------------------------------------------------------------------------
// Reduce norm partials (fixed order, deterministic)
// ---------------------------------------------------------------------------
__global__ void reduce_norms_kernel()
{
    int idx = blockIdx.x * blockDim.x + threadIdx.x;
    if (idx < BNR) {
        float s = 0.f;
        #pragma unroll
        for (int z = 0; z < SPLITS; z++) s += g_pnp[z * BNR + idx];
        g_pnorm[idx] = s;
    } else if (idx < BNR + TT) {
        int t = idx - BNR;
        float s = 0.f;
        #pragma unroll
        for (int z = 0; z < SPLITS; z++) s += g_tnp[z * TT + t];
        g_tnorm[t] = s;
    }
}

// ---------------------------------------------------------------------------
// Assemble C = 2 * dice_score + focal class cost (inline), float4-vectorized.
// ---------------------------------------------------------------------------
__global__ void assemble_kernel(const float* __restrict__ logits,
                                const int* __restrict__ tgt_ids,
                                float* __restrict__ out)
{
    int idx = blockIdx.x * blockDim.x + threadIdx.x;
    if (idx >= BNR*TT/4) return;
    int row = idx / (TT/4), t4 = idx % (TT/4);

    float4 dot = make_float4(0.f, 0.f, 0.f, 0.f);
    #pragma unroll
    for (int s = 0; s < SPLITS; s++) {
        float4 v = *(const float4*)(g_part + ((size_t)s * BNR + row) * TT + t4 * 4);
        dot.x += v.x; dot.y += v.y; dot.z += v.z; dot.w += v.w;
    }
    float pn = g_pnorm[row];
    const float* lrow = logits + row * KCLS;

    float4 res;
    float* dp = (float*)&dot;
    float* rp = (float*)&res;
    #pragma unroll
    for (int e = 0; e < 4; e++) {
        int t = t4 * 4 + e;
        float den = pn + g_tnorm[t];
        float score = -((2.f * dp[e] + 1e-4f) / (den + 1e-4f));
        float x = lrow[tgt_ids[t]];
        float pp = 1.f / (1.f + expf(-x));
        float neg = 0.75f * pp * pp * (-logf(1.f - pp + 1e-8f));
        float pos = 0.25f * (1.f - pp) * (1.f - pp) * (-logf(pp + 1e-8f));
        float c = 2.f * score + (pos - neg);
        if (!isfinite(c)) c = 0.f;
        rp[e] = c;
    }
    *(float4*)(out + (size_t)row * TT + t4 * 4) = res;
}

// ---------------------------------------------------------------------------
// Hungarian (Jonker-Volgenant) — absolute-distance form, fp32 internal,
// REDUX warp reductions. Selection order matches the reference up to fp32
// rounding of path costs (same perturbation class as the C matrix itself);
// first-index tie-breaks preserved via min-key-then-min-j REDUX pair.
// ---------------------------------------------------------------------------
__device__ __forceinline__ uint32_t f2k(float x)
{
    int b = __float_as_int(x);
    return (uint32_t)b ^ ((b < 0) ? 0xFFFFFFFFu : 0x80000000u);
}
__device__ __forceinline__ float k2f(uint32_t k)
{
    int b = (int)(k ^ (((int)k < 0) ? 0x80000000u : 0xFFFFFFFFu));
    return __int_as_float(b);
}

__global__ void hungarian_kernel(const float* __restrict__ C, float* __restrict__ out)
{
    int b = blockIdx.x;
    int lane = threadIdx.x;

    __shared__ float cost[MT][NN];
    __shared__ float u[MT+1];
    __shared__ int p[NN+1], way[NN+1];

    for (int idx = lane; idx < MT*NN; idx += 32) {
        int r = idx / NN, c = idx % NN;
        cost[r][c] = C[(size_t)(b*NN + c) * TT + b*MT + r];
    }
    for (int j = lane; j <= NN; j += 32) { p[j] = 0; way[j] = 0; }
    for (int j = lane; j <= MT; j += 32) u[j] = 0.0f;
    float v[4] = {0.f, 0.f, 0.f, 0.f};
    const int jcol[4] = {lane + 1, lane + 33, lane + 65, lane + 97};
    const uint32_t KINF = 0xFFFFFFFFu;
    __syncwarp();

    for (int i = 1; i <= MT; i++) {
        uint32_t absk[4] = {KINF, KINF, KINF, KINF};
        float dj[4] = {0.f, 0.f, 0.f, 0.f};
        int usedm = (lane >= 4) ? 8 : 0;       // kk=3 invalid for lane>=4 (j>100)
        float Dprev = 0.f;
        int j0 = 0, i0 = i;

        while (true) {
            // mark previously selected column as used; record its join-S
            if (j0 > 0) {
                int ol = (j0 - 1) & 31, ok = (j0 - 1) >> 5;
                if (lane == ol) {
                    #pragma unroll
                    for (int kk = 0; kk < 4; kk++)
                        if (kk == ok) { usedm |= 1 << kk; dj[kk] = Dprev; }
                }
            }
            float off = Dprev - u[i0];

            // relax unused columns: abs[j] = min(abs[j], cost - u0 - v0 + S_prev)
            #pragma unroll
            for (int kk = 0; kk < 4; kk++) {
                if (!((usedm >> kk) & 1)) {
                    float cur = (cost[i0 - 1][jcol[kk] - 1] - v[kk]) + off;
                    uint32_t ck = f2k(cur);
                    if (ck < absk[kk]) { absk[kk] = ck; way[jcol[kk]] = j0; }
                }
            }

            // lane-local min over unused (kk ascending = j ascending; strict <
            // keeps first), then warp min-key and min-j-among-min-key via REDUX
            uint32_t bk = KINF;
            uint32_t bj = NN + 2;
            #pragma unroll
            for (int kk = 0; kk < 4; kk++) {
                if (!((usedm >> kk) & 1) && absk[kk] < bk) {
                    bk = absk[kk]; bj = (uint32_t)jcol[kk];
                }
            }
            uint32_t kmin = __reduce_min_sync(0xffffffffu, bk);
            uint32_t j1 = __reduce_min_sync(0xffffffffu, (bk == kmin) ? bj : 0x7FFFFFFFu);

            Dprev = k2f(kmin);            // S_k = abs[j1]
            j0 = (int)j1;
            i0 = p[j0];
            if (i0 == 0) break;
        }

        float Slast = Dprev;
        // deferred potential updates (match reference's end-of-search u/v)
        if (lane == 0) u[i] += Slast;
        #pragma unroll
        for (int kk = 0; kk < 4; kk++) {
            if (((usedm >> kk) & 1) && !(kk == 3 && lane >= 4)) {
                float du = Slast - dj[kk];
                int r = p[jcol[kk]];       // distinct rows across lanes
                u[r] += du;
                v[kk] -= du;
            }
        }
        __syncwarp();
        if (lane == 0) {                  // augment along way[] chain
            p[0] = i;
            int jj = j0;
            while (jj) { int jp = way[jj]; p[jj] = p[jp]; jj = jp; }
        }
        __syncwarp();
    }

    if (lane == 0) {
        int k = 0;
        for (int j = 1; j <= NN; j++) {
            if (p[j] != 0) {
                out[(size_t)BNR*TT + b*MT + k]            = (float)(j - 1);
                out[(size_t)BNR*TT + BB*MT + b*MT + k]    = (float)(p[j] - 1);
                k++;
            }
        }
    }
}

// ---------------------------------------------------------------------------
extern "C" void kernel_launch(void* const* d_in, const int* in_sizes, int n_in,
                              void* d_out, int out_size)
{
    const float* pred_masks   = (const float*)d_in[0];   // (8,100,160,160)
    const float* pred_logits  = (const float*)d_in[1];   // (8,100,80)
    const float* target_masks = (const float*)d_in[2];   // (160,160,160)
    const int*   tgt_ids      = (const int*)d_in[3];     // (160,)
    float* out = (float*)d_out;                           // C(128000) | rows(160) | cols(160)

    cudaFuncSetAttribute(gemm_tf32, cudaFuncAttributeMaxDynamicSharedMemorySize,
                         SMEM_BYTES);

    gemm_tf32<<<dim3(7, SPLITS), 512, SMEM_BYTES>>>(pred_masks, target_masks);

    reduce_norms_kernel<<<4, 256>>>();

    assemble_kernel<<<(BNR*TT/4 + 255)/256, 256>>>(pred_logits, tgt_ids, out);

    hungarian_kernel<<<BB, 32>>>(out, out);
}